// round 1
// baseline (speedup 1.0000x reference)
#include <cuda_runtime.h>
#include <math.h>

// Problem constants (fixed by the dataset: x is (16, 1024, 768), h=w=32)
#define BDIM 16
#define HDIM 32
#define WDIM 32
#define TDIM (HDIM * WDIM)          // 1024
#define CDIM 768
#define MROWS (BDIM * TDIM)         // 16384
#define QC (CDIM / 4)               // 192  (gamma = 0.25, 4*QC == CDIM, no "rest")

#define NELEM ((size_t)MROWS * CDIM)   // 12,582,912

// ---------------------------------------------------------------------------
// Scratch (device globals; no allocation allowed)
// ---------------------------------------------------------------------------
__device__ float g_xk[NELEM];
__device__ float g_xv[NELEM];
__device__ float g_xr[NELEM];
__device__ float g_k [NELEM];
__device__ float g_v [NELEM];
__device__ float g_sr[NELEM];
__device__ float g_y [NELEM];
__device__ float g_z [NELEM];

__device__ __forceinline__ float* sel_buf(int sel) {
    switch (sel) {
        case 0: return g_xk;
        case 1: return g_xv;
        case 2: return g_xr;
        case 3: return g_k;
        case 4: return g_v;
        case 5: return g_sr;
        case 6: return g_y;
        default: return g_z;
    }
}

// ---------------------------------------------------------------------------
// Stage 1: q_shift + token mixes  (writes g_xk, g_xv, g_xr)
// ---------------------------------------------------------------------------
__global__ void shift_mix_kernel(const float* __restrict__ x,
                                 const float* __restrict__ mix_k,
                                 const float* __restrict__ mix_v,
                                 const float* __restrict__ mix_r) {
    size_t idx = (size_t)blockIdx.x * blockDim.x + threadIdx.x;
    if (idx >= NELEM) return;
    int c  = (int)(idx % CDIM);
    int sp = (int)(idx / CDIM);         // b*T + t, t = h*W + w
    int wq = sp % WDIM;
    int hq = (sp / WDIM) % HDIM;

    float xx = 0.0f;
    if (c < QC) {                       // shift from w-1
        if (wq > 0)         xx = x[idx - CDIM];
    } else if (c < 2 * QC) {            // shift from w+1
        if (wq < WDIM - 1)  xx = x[idx + CDIM];
    } else if (c < 3 * QC) {            // shift from h-1
        if (hq > 0)         xx = x[idx - (size_t)WDIM * CDIM];
    } else {                            // shift from h+1
        if (hq < HDIM - 1)  xx = x[idx + (size_t)WDIM * CDIM];
    }

    float xc = x[idx];
    float mk = mix_k[c];
    float mv = mix_v[c];
    float mr = mix_r[c];
    g_xk[idx] = xc * mk + xx * (1.0f - mk);
    g_xv[idx] = xc * mv + xx * (1.0f - mv);
    g_xr[idx] = xc * mr + xx * (1.0f - mr);
}

// ---------------------------------------------------------------------------
// Stage 2/5: SGEMM  C[M,N] = A[M,K] @ B[K,N]   (row-major, fp32)
// 128x128 block tile, 8 K-slice, 256 threads, 8x8 per-thread microtile.
// act: 0 = none, 1 = sigmoid.
// aSel / cSel pick device-global buffers; cOut overrides C when cSel < 0.
// ---------------------------------------------------------------------------
#define BM 128
#define BN 128
#define BK 8
#define TM 8
#define TN 8

__global__ __launch_bounds__(256, 2)
void sgemm_kernel(int aSel, const float* __restrict__ Bw,
                  int cSel, float* __restrict__ cOut,
                  int act) {
    const float* __restrict__ A = sel_buf(aSel);
    float* __restrict__ C = (cSel >= 0) ? sel_buf(cSel) : cOut;

    const int K = CDIM;
    const int N = CDIM;

    __shared__ float As[BK][BM];
    __shared__ float Bs[BK][BN];

    int tid = threadIdx.x;
    int tx = tid % 16;          // N-tile coord
    int ty = tid / 16;          // M-tile coord

    const float* Ab = A + (size_t)blockIdx.y * BM * K;
    const float* Bb = Bw + (size_t)blockIdx.x * BN;

    // load mapping
    int aRow = tid >> 1;                // 0..127
    int aCol = (tid & 1) * 4;           // 0 or 4
    int bRow = tid >> 5;                // 0..7
    int bCol = (tid & 31) * 4;          // 0..124

    float acc[TM][TN];
#pragma unroll
    for (int i = 0; i < TM; i++)
#pragma unroll
        for (int j = 0; j < TN; j++) acc[i][j] = 0.0f;

    for (int k0 = 0; k0 < K; k0 += BK) {
        float4 a4 = *(const float4*)(Ab + (size_t)aRow * K + k0 + aCol);
        As[aCol + 0][aRow] = a4.x;
        As[aCol + 1][aRow] = a4.y;
        As[aCol + 2][aRow] = a4.z;
        As[aCol + 3][aRow] = a4.w;
        float4 b4 = *(const float4*)(Bb + (size_t)(k0 + bRow) * N + bCol);
        *(float4*)&Bs[bRow][bCol] = b4;
        __syncthreads();

#pragma unroll
        for (int kk = 0; kk < BK; kk++) {
            float ar[TM], br[TN];
            *(float4*)&ar[0] = *(const float4*)&As[kk][ty * TM];
            *(float4*)&ar[4] = *(const float4*)&As[kk][ty * TM + 4];
            *(float4*)&br[0] = *(const float4*)&Bs[kk][tx * TN];
            *(float4*)&br[4] = *(const float4*)&Bs[kk][tx * TN + 4];
#pragma unroll
            for (int i = 0; i < TM; i++)
#pragma unroll
                for (int j = 0; j < TN; j++)
                    acc[i][j] = fmaf(ar[i], br[j], acc[i][j]);
        }
        __syncthreads();
    }

#pragma unroll
    for (int i = 0; i < TM; i++) {
        size_t m = (size_t)blockIdx.y * BM + ty * TM + i;
#pragma unroll
        for (int j = 0; j < TN; j += 4) {
            int n = blockIdx.x * BN + tx * TN + j;
            float4 o;
            o.x = acc[i][j + 0];
            o.y = acc[i][j + 1];
            o.z = acc[i][j + 2];
            o.w = acc[i][j + 3];
            if (act == 1) {
                o.x = 1.0f / (1.0f + __expf(-o.x));
                o.y = 1.0f / (1.0f + __expf(-o.y));
                o.z = 1.0f / (1.0f + __expf(-o.z));
                o.w = 1.0f / (1.0f + __expf(-o.w));
            }
            *(float4*)(C + m * N + n) = o;
        }
    }
}

// ---------------------------------------------------------------------------
// Stage 3: WKV sequential scan over T per (b, c) lane.  g_k, g_v -> g_y
// ---------------------------------------------------------------------------
__global__ void wkv_kernel(const float* __restrict__ spatial_decay,
                           const float* __restrict__ spatial_first) {
    int tid = blockIdx.x * blockDim.x + threadIdx.x;
    if (tid >= BDIM * CDIM) return;
    int c = tid % CDIM;
    int b = tid / CDIM;

    const float inv_t = 1.0f / (float)TDIM;
    float w = spatial_decay[c] * inv_t;
    float u = spatial_first[c] * inv_t;

    float p = 0.0f, q = 0.0f, o = -1e38f;
    const float* kp = g_k + (size_t)b * TDIM * CDIM + c;
    const float* vp = g_v + (size_t)b * TDIM * CDIM + c;
    float*       yp = g_y + (size_t)b * TDIM * CDIM + c;

    for (int t = 0; t < TDIM; t++) {
        float kt = kp[(size_t)t * CDIM];
        float vt = vp[(size_t)t * CDIM];

        float uk = u + kt;
        float no = fmaxf(o, uk);
        float Aa = __expf(o - no);
        float Bb = __expf(uk - no);
        yp[(size_t)t * CDIM] = (Aa * p + Bb * vt) / (Aa * q + Bb);

        float wo = w + o;
        float no2 = fmaxf(wo, kt);
        float A2 = __expf(wo - no2);
        float B2 = __expf(kt - no2);
        p = A2 * p + B2 * vt;
        q = A2 * q + B2;
        o = no2;
    }
}

// ---------------------------------------------------------------------------
// Stage 4: layernorm(y) * sigmoid(r)  ->  g_z     (one block per row)
// ---------------------------------------------------------------------------
__device__ __forceinline__ float block_reduce_sum(float val) {
    __shared__ float sh[8];
    __shared__ float total;
    int lane = threadIdx.x & 31;
    int wid  = threadIdx.x >> 5;
    __syncthreads();   // protect sh across back-to-back calls
#pragma unroll
    for (int off = 16; off > 0; off >>= 1)
        val += __shfl_xor_sync(0xffffffffu, val, off);
    if (lane == 0) sh[wid] = val;
    __syncthreads();
    if (wid == 0) {
        float v2 = (lane < 8) ? sh[lane] : 0.0f;
#pragma unroll
        for (int off = 4; off > 0; off >>= 1)
            v2 += __shfl_xor_sync(0xffffffffu, v2, off);
        if (lane == 0) total = v2;
    }
    __syncthreads();
    return total;
}

__global__ void ln_gate_kernel(const float* __restrict__ ln_g,
                               const float* __restrict__ ln_b) {
    int row = blockIdx.x;                    // 0..MROWS-1
    int tid = threadIdx.x;                   // 256 threads, 3 elems each
    const float* yrow  = g_y  + (size_t)row * CDIM;
    const float* srrow = g_sr + (size_t)row * CDIM;
    float*       zrow  = g_z  + (size_t)row * CDIM;

    float vals[3];
    float s = 0.0f;
#pragma unroll
    for (int i = 0; i < 3; i++) {
        vals[i] = yrow[tid + i * 256];
        s += vals[i];
    }
    s = block_reduce_sum(s);
    float mu = s * (1.0f / CDIM);

    float d[3];
    float ss = 0.0f;
#pragma unroll
    for (int i = 0; i < 3; i++) {
        d[i] = vals[i] - mu;
        ss += d[i] * d[i];
    }
    ss = block_reduce_sum(ss);
    float rstd = rsqrtf(ss * (1.0f / CDIM) + 1e-5f);

#pragma unroll
    for (int i = 0; i < 3; i++) {
        int c = tid + i * 256;
        zrow[c] = srrow[c] * (d[i] * rstd * ln_g[c] + ln_b[c]);
    }
}

// ---------------------------------------------------------------------------
// Launch
// ---------------------------------------------------------------------------
extern "C" void kernel_launch(void* const* d_in, const int* in_sizes, int n_in,
                              void* d_out, int out_size) {
    const float* x   = (const float*)d_in[0];
    // d_in[1], d_in[2] are h, w scalars (compile-time constants here)
    const float* sd  = (const float*)d_in[3];
    const float* sf  = (const float*)d_in[4];
    const float* mk  = (const float*)d_in[5];
    const float* mv  = (const float*)d_in[6];
    const float* mr  = (const float*)d_in[7];
    const float* Wk  = (const float*)d_in[8];
    const float* Wv  = (const float*)d_in[9];
    const float* Wr  = (const float*)d_in[10];
    const float* Wo  = (const float*)d_in[11];
    const float* lg  = (const float*)d_in[12];
    const float* lb  = (const float*)d_in[13];
    float* out = (float*)d_out;

    // 1. q_shift + mixes
    {
        int threads = 256;
        int blocks = (int)((NELEM + threads - 1) / threads);
        shift_mix_kernel<<<blocks, threads>>>(x, mk, mv, mr);
    }

    // 2. k / v / sr GEMMs
    dim3 gemm_grid(CDIM / BN, MROWS / BM);   // (6, 128)
    sgemm_kernel<<<gemm_grid, 256>>>(0, Wk, 3, nullptr, 0);   // g_xk @ Wk -> g_k
    sgemm_kernel<<<gemm_grid, 256>>>(1, Wv, 4, nullptr, 0);   // g_xv @ Wv -> g_v
    sgemm_kernel<<<gemm_grid, 256>>>(2, Wr, 5, nullptr, 1);   // sigmoid(g_xr @ Wr) -> g_sr

    // 3. WKV scan
    wkv_kernel<<<(BDIM * CDIM) / 64, 64>>>(sd, sf);

    // 4. layernorm + sigmoid gate
    ln_gate_kernel<<<MROWS, 256>>>(lg, lb);

    // 5. output projection -> d_out
    sgemm_kernel<<<gemm_grid, 256>>>(7, Wo, -1, out, 0);      // g_z @ Wo -> out
}

// round 3
// speedup vs baseline: 1.8280x; 1.8280x over previous
#include <cuda_runtime.h>
#include <cuda_bf16.h>
#include <stdint.h>
#include <math.h>

// Problem constants (fixed by dataset: x is (16, 1024, 768), h=w=32)
#define BDIM 16
#define HDIM 32
#define WDIM 32
#define TDIM (HDIM * WDIM)          // 1024
#define CDIM 768
#define MROWS (BDIM * TDIM)         // 16384
#define QC (CDIM / 4)               // 192

#define NELEM ((size_t)MROWS * CDIM)   // 12,582,912

// ---------------------------------------------------------------------------
// Scratch (device globals; no allocation allowed)
// ---------------------------------------------------------------------------
// A-side bf16 hi/lo: 0=xk, 1=xv, 2=xr, 3=z(gated ln output)
__device__ __nv_bfloat16 g_ah[4][NELEM];
__device__ __nv_bfloat16 g_al[4][NELEM];
// Transposed weights [N][K] bf16 hi/lo: 0=Wk, 1=Wv, 2=Wr, 3=Wo
__device__ __nv_bfloat16 g_wh[4][CDIM * CDIM];
__device__ __nv_bfloat16 g_wl[4][CDIM * CDIM];
// fp32 intermediates
__device__ float g_k [NELEM];
__device__ float g_v [NELEM];
__device__ float g_sr[NELEM];
__device__ float g_y [NELEM];

// ---------------------------------------------------------------------------
// PTX helpers (base sm_103-compatible: mma.sync / ldmatrix / cp.async)
// ---------------------------------------------------------------------------
__device__ __forceinline__ uint32_t smem_u32(const void* p) {
    uint32_t a;
    asm("{ .reg .u64 t; cvta.to.shared.u64 t, %1; cvt.u32.u64 %0, t; }"
        : "=r"(a) : "l"(p));
    return a;
}

__device__ __forceinline__ void ldsm4(uint32_t& r0, uint32_t& r1,
                                      uint32_t& r2, uint32_t& r3, uint32_t addr) {
    asm volatile("ldmatrix.sync.aligned.m8n8.x4.shared.b16 {%0,%1,%2,%3}, [%4];"
                 : "=r"(r0), "=r"(r1), "=r"(r2), "=r"(r3) : "r"(addr));
}

__device__ __forceinline__ void mma16816(float* c, const uint32_t* a, const uint32_t* b) {
    asm volatile(
        "mma.sync.aligned.m16n8k16.row.col.f32.bf16.bf16.f32 "
        "{%0,%1,%2,%3}, {%4,%5,%6,%7}, {%8,%9}, {%0,%1,%2,%3};"
        : "+f"(c[0]), "+f"(c[1]), "+f"(c[2]), "+f"(c[3])
        : "r"(a[0]), "r"(a[1]), "r"(a[2]), "r"(a[3]), "r"(b[0]), "r"(b[1]));
}

__device__ __forceinline__ void cp16(uint32_t saddr, const void* gptr) {
    asm volatile("cp.async.cg.shared.global [%0], [%1], 16;"
                 :: "r"(saddr), "l"(gptr));
}
#define CP_COMMIT() asm volatile("cp.async.commit_group;" ::: "memory")
#define CP_WAIT2()  asm volatile("cp.async.wait_group 2;" ::: "memory")

// ---------------------------------------------------------------------------
// Stage 0: weight transpose + bf16 hi/lo split:  Wt[n][k] = W[k][n]
// ---------------------------------------------------------------------------
__global__ void wtrans_kernel(const float* __restrict__ W0, const float* __restrict__ W1,
                              const float* __restrict__ W2, const float* __restrict__ W3) {
    __shared__ float s[32][33];
    const float* W = (blockIdx.z == 0) ? W0 : (blockIdx.z == 1) ? W1
                   : (blockIdx.z == 2) ? W2 : W3;
    int n0 = blockIdx.x * 32, k0 = blockIdx.y * 32;
    int tx = threadIdx.x, ty = threadIdx.y;   // 32 x 8
#pragma unroll
    for (int i = 0; i < 4; i++) {
        int kk = ty + i * 8;
        s[kk][tx] = W[(size_t)(k0 + kk) * CDIM + n0 + tx];
    }
    __syncthreads();
#pragma unroll
    for (int i = 0; i < 4; i++) {
        int nn = ty + i * 8;
        float v = s[tx][nn];                  // = W[k0+tx][n0+nn]
        size_t o = (size_t)(n0 + nn) * CDIM + k0 + tx;
        __nv_bfloat16 h = __float2bfloat16(v);
        g_wh[blockIdx.z][o] = h;
        g_wl[blockIdx.z][o] = __float2bfloat16(v - __bfloat162float(h));
    }
}

// ---------------------------------------------------------------------------
// Stage 1: q_shift + token mixes -> bf16 hi/lo (xk, xv, xr)
// ---------------------------------------------------------------------------
__device__ __forceinline__ void store_hl(int sel, size_t idx, float v) {
    __nv_bfloat16 h = __float2bfloat16(v);
    g_ah[sel][idx] = h;
    g_al[sel][idx] = __float2bfloat16(v - __bfloat162float(h));
}

__global__ void shift_mix_kernel(const float* __restrict__ x,
                                 const float* __restrict__ mix_k,
                                 const float* __restrict__ mix_v,
                                 const float* __restrict__ mix_r) {
    size_t idx = (size_t)blockIdx.x * blockDim.x + threadIdx.x;
    if (idx >= NELEM) return;
    int c  = (int)(idx % CDIM);
    int sp = (int)(idx / CDIM);
    int wq = sp % WDIM;
    int hq = (sp / WDIM) % HDIM;

    float xx = 0.0f;
    if (c < QC) {
        if (wq > 0)         xx = x[idx - CDIM];
    } else if (c < 2 * QC) {
        if (wq < WDIM - 1)  xx = x[idx + CDIM];
    } else if (c < 3 * QC) {
        if (hq > 0)         xx = x[idx - (size_t)WDIM * CDIM];
    } else {
        if (hq < HDIM - 1)  xx = x[idx + (size_t)WDIM * CDIM];
    }

    float xc = x[idx];
    float mk = mix_k[c], mv = mix_v[c], mr = mix_r[c];
    store_hl(0, idx, xc * mk + xx * (1.0f - mk));
    store_hl(1, idx, xc * mv + xx * (1.0f - mv));
    store_hl(2, idx, xc * mr + xx * (1.0f - mr));
}

// ---------------------------------------------------------------------------
// Stage 2/5: bf16 tensor-core GEMM via mma.sync (3-pass hi/lo split).
// C[M,N] = A[M,K] @ W[K,N].  CTA tile 128x128, 8 warps (2x4 -> 64x32 each),
// BK=32, 3-stage cp.async pipeline.  act: 1 = sigmoid on output.
// ---------------------------------------------------------------------------
#define PITCH 80                          // bytes per smem row (64 data + 16 pad)
#define TILEB (128 * PITCH)               // 10240 per array
#define STAGEB (4 * TILEB)                // 40960: [Ah | Al | Bh | Bl]
#define NSTAGE 3
#define SM_GEMM (NSTAGE * STAGEB)         // 122880

__global__ __launch_bounds__(256, 1)
void tc_gemm_kernel(int aSel, int wSel, int cSel, float* __restrict__ cOut, int act) {
    extern __shared__ char smem[];
    const uint32_t sb = smem_u32(smem);
    const int tid = threadIdx.x;
    const int w = tid >> 5, l = tid & 31;
    const int wm = w >> 2, wn = w & 3;

    const __nv_bfloat16* __restrict__ Ah = g_ah[aSel];
    const __nv_bfloat16* __restrict__ Al = g_al[aSel];
    const __nv_bfloat16* __restrict__ Wh = g_wh[wSel];
    const __nv_bfloat16* __restrict__ Wl = g_wl[wSel];
    float* __restrict__ C = (cSel == 0) ? g_k : (cSel == 1) ? g_v
                          : (cSel == 2) ? g_sr : cOut;

    const int mrow0 = blockIdx.y * 128;
    const int ncol0 = blockIdx.x * 128;

    float acc[4][4][4];
#pragma unroll
    for (int i = 0; i < 4; i++)
#pragma unroll
        for (int j = 0; j < 4; j++)
#pragma unroll
            for (int q = 0; q < 4; q++) acc[i][j][q] = 0.0f;

    // cp.async mapping: 2 x 256 chunk ids -> (row, 16B chunk)
    auto issue = [&](int kc, int st) {
        if (kc < 24) {
            uint32_t s0 = sb + st * STAGEB;
#pragma unroll
            for (int j = 0; j < 2; j++) {
                int id = tid + j * 256;          // 0..511
                int row = id >> 2, cc = id & 3;
                size_t gA = (size_t)(mrow0 + row) * CDIM + kc * 32 + cc * 8;
                size_t gB = (size_t)(ncol0 + row) * CDIM + kc * 32 + cc * 8;
                uint32_t so = (uint32_t)(row * PITCH + cc * 16);
                cp16(s0 + 0 * TILEB + so, Ah + gA);
                cp16(s0 + 1 * TILEB + so, Al + gA);
                cp16(s0 + 2 * TILEB + so, Wh + gB);
                cp16(s0 + 3 * TILEB + so, Wl + gB);
            }
        }
        CP_COMMIT();
    };

    issue(0, 0); issue(1, 1); issue(2, 2);

    // ldmatrix per-lane invariants
    const uint32_t aOff = (uint32_t)((wm * 64 + (l & 15)) * PITCH + (l >> 4) * 16);
    const uint32_t bOff = (uint32_t)(2 * TILEB +
                    (wn * 32 + ((l & 7) | ((l >> 4) << 3))) * PITCH + ((l >> 3) & 1) * 16);

    for (int kc = 0; kc < 24; kc++) {
        int st = kc % NSTAGE;
        CP_WAIT2();
        __syncthreads();
        uint32_t s0 = sb + st * STAGEB;
#pragma unroll
        for (int ks = 0; ks < 2; ks++) {
            uint32_t ah[4][4], al[4][4], bh[2][4], bl[2][4];
            uint32_t aA = s0 + aOff + ks * 32;
            uint32_t bA = s0 + bOff + ks * 32;
#pragma unroll
            for (int am = 0; am < 4; am++) {
                ldsm4(ah[am][0], ah[am][1], ah[am][2], ah[am][3],
                      aA + am * 16 * PITCH);
                ldsm4(al[am][0], al[am][1], al[am][2], al[am][3],
                      aA + am * 16 * PITCH + TILEB);
            }
#pragma unroll
            for (int bn = 0; bn < 2; bn++) {
                ldsm4(bh[bn][0], bh[bn][1], bh[bn][2], bh[bn][3],
                      bA + bn * 16 * PITCH);
                ldsm4(bl[bn][0], bl[bn][1], bl[bn][2], bl[bn][3],
                      bA + bn * 16 * PITCH + TILEB);
            }
#pragma unroll
            for (int am = 0; am < 4; am++)
#pragma unroll
                for (int an = 0; an < 4; an++) {
                    const uint32_t* bhp = &bh[an >> 1][(an & 1) * 2];
                    const uint32_t* blp = &bl[an >> 1][(an & 1) * 2];
                    mma16816(acc[am][an], ah[am], bhp);
                    mma16816(acc[am][an], ah[am], blp);
                    mma16816(acc[am][an], al[am], bhp);
                }
        }
        __syncthreads();
        issue(kc + NSTAGE, st);
    }

    // Epilogue: C frag: (c0,c1) @ row l/4, col (l&3)*2; (c2,c3) @ row l/4+8.
#pragma unroll
    for (int am = 0; am < 4; am++) {
        int r0 = mrow0 + wm * 64 + am * 16 + (l >> 2);
#pragma unroll
        for (int an = 0; an < 4; an++) {
            int cc = ncol0 + wn * 32 + an * 8 + (l & 3) * 2;
            float v0 = acc[am][an][0], v1 = acc[am][an][1];
            float v2 = acc[am][an][2], v3 = acc[am][an][3];
            if (act == 1) {
                v0 = 1.0f / (1.0f + __expf(-v0));
                v1 = 1.0f / (1.0f + __expf(-v1));
                v2 = 1.0f / (1.0f + __expf(-v2));
                v3 = 1.0f / (1.0f + __expf(-v3));
            }
            *(float2*)(C + (size_t)r0 * CDIM + cc)       = make_float2(v0, v1);
            *(float2*)(C + (size_t)(r0 + 8) * CDIM + cc) = make_float2(v2, v3);
        }
    }
}

// ---------------------------------------------------------------------------
// Stage 3: WKV sequential scan over T per (b, c) lane.  g_k, g_v -> g_y
// ---------------------------------------------------------------------------
__global__ void wkv_kernel(const float* __restrict__ spatial_decay,
                           const float* __restrict__ spatial_first) {
    int tid = blockIdx.x * blockDim.x + threadIdx.x;
    if (tid >= BDIM * CDIM) return;
    int c = tid % CDIM;
    int b = tid / CDIM;

    const float inv_t = 1.0f / (float)TDIM;
    float w = spatial_decay[c] * inv_t;
    float u = spatial_first[c] * inv_t;

    float p = 0.0f, q = 0.0f, o = -1e38f;
    const float* kp = g_k + (size_t)b * TDIM * CDIM + c;
    const float* vp = g_v + (size_t)b * TDIM * CDIM + c;
    float*       yp = g_y + (size_t)b * TDIM * CDIM + c;

    for (int t = 0; t < TDIM; t++) {
        float kt = kp[(size_t)t * CDIM];
        float vt = vp[(size_t)t * CDIM];

        float uk = u + kt;
        float no = fmaxf(o, uk);
        float Aa = __expf(o - no);
        float Bb = __expf(uk - no);
        yp[(size_t)t * CDIM] = (Aa * p + Bb * vt) / (Aa * q + Bb);

        float wo = w + o;
        float no2 = fmaxf(wo, kt);
        float A2 = __expf(wo - no2);
        float B2 = __expf(kt - no2);
        p = A2 * p + B2 * vt;
        q = A2 * q + B2;
        o = no2;
    }
}

// ---------------------------------------------------------------------------
// Stage 4: layernorm(y) * sigmoid_r -> z (bf16 hi/lo), one block per row
// ---------------------------------------------------------------------------
__device__ __forceinline__ float block_reduce_sum(float val) {
    __shared__ float sh[8];
    __shared__ float total;
    int lane = threadIdx.x & 31;
    int wid  = threadIdx.x >> 5;
    __syncthreads();
#pragma unroll
    for (int off = 16; off > 0; off >>= 1)
        val += __shfl_xor_sync(0xffffffffu, val, off);
    if (lane == 0) sh[wid] = val;
    __syncthreads();
    if (wid == 0) {
        float v2 = (lane < 8) ? sh[lane] : 0.0f;
#pragma unroll
        for (int off = 4; off > 0; off >>= 1)
            v2 += __shfl_xor_sync(0xffffffffu, v2, off);
        if (lane == 0) total = v2;
    }
    __syncthreads();
    return total;
}

__global__ void ln_gate_kernel(const float* __restrict__ ln_g,
                               const float* __restrict__ ln_b) {
    int row = blockIdx.x;
    int tid = threadIdx.x;                   // 256 threads, 3 elems each
    const float* yrow  = g_y  + (size_t)row * CDIM;
    const float* srrow = g_sr + (size_t)row * CDIM;
    size_t base = (size_t)row * CDIM;

    float vals[3];
    float s = 0.0f;
#pragma unroll
    for (int i = 0; i < 3; i++) {
        vals[i] = yrow[tid + i * 256];
        s += vals[i];
    }
    s = block_reduce_sum(s);
    float mu = s * (1.0f / CDIM);

    float d[3];
    float ss = 0.0f;
#pragma unroll
    for (int i = 0; i < 3; i++) {
        d[i] = vals[i] - mu;
        ss += d[i] * d[i];
    }
    ss = block_reduce_sum(ss);
    float rstd = rsqrtf(ss * (1.0f / CDIM) + 1e-5f);

#pragma unroll
    for (int i = 0; i < 3; i++) {
        int c = tid + i * 256;
        float zv = srrow[c] * (d[i] * rstd * ln_g[c] + ln_b[c]);
        store_hl(3, base + c, zv);
    }
}

// ---------------------------------------------------------------------------
// Launch
// ---------------------------------------------------------------------------
extern "C" void kernel_launch(void* const* d_in, const int* in_sizes, int n_in,
                              void* d_out, int out_size) {
    const float* x   = (const float*)d_in[0];
    const float* sd  = (const float*)d_in[3];
    const float* sf  = (const float*)d_in[4];
    const float* mk  = (const float*)d_in[5];
    const float* mv  = (const float*)d_in[6];
    const float* mr  = (const float*)d_in[7];
    const float* Wk  = (const float*)d_in[8];
    const float* Wv  = (const float*)d_in[9];
    const float* Wr  = (const float*)d_in[10];
    const float* Wo  = (const float*)d_in[11];
    const float* lg  = (const float*)d_in[12];
    const float* lb  = (const float*)d_in[13];
    float* out = (float*)d_out;

    cudaFuncSetAttribute(tc_gemm_kernel,
                         cudaFuncAttributeMaxDynamicSharedMemorySize, SM_GEMM);

    // 0. transpose + split weights
    {
        dim3 blk(32, 8);
        dim3 grd(CDIM / 32, CDIM / 32, 4);
        wtrans_kernel<<<grd, blk>>>(Wk, Wv, Wr, Wo);
    }

    // 1. q_shift + mixes -> bf16 hi/lo
    {
        int threads = 256;
        int blocks = (int)((NELEM + threads - 1) / threads);
        shift_mix_kernel<<<blocks, threads>>>(x, mk, mv, mr);
    }

    // 2. k / v / sr GEMMs (tensor cores)
    dim3 gg(CDIM / 128, MROWS / 128);   // (6, 128)
    tc_gemm_kernel<<<gg, 256, SM_GEMM>>>(0, 0, 0, nullptr, 0);   // xk @ Wk -> g_k
    tc_gemm_kernel<<<gg, 256, SM_GEMM>>>(1, 1, 1, nullptr, 0);   // xv @ Wv -> g_v
    tc_gemm_kernel<<<gg, 256, SM_GEMM>>>(2, 2, 2, nullptr, 1);   // sigmoid(xr @ Wr) -> g_sr

    // 3. WKV scan
    wkv_kernel<<<(BDIM * CDIM) / 64, 64>>>(sd, sf);

    // 4. layernorm + gate -> z (bf16 hi/lo)
    ln_gate_kernel<<<MROWS, 256>>>(lg, lb);

    // 5. output projection -> d_out
    tc_gemm_kernel<<<gg, 256, SM_GEMM>>>(3, 3, 3, out, 0);       // z @ Wo -> out
}

// round 4
// speedup vs baseline: 3.4825x; 1.9051x over previous
#include <cuda_runtime.h>
#include <cuda_bf16.h>
#include <stdint.h>
#include <math.h>

// Problem constants (fixed by dataset: x is (16, 1024, 768), h=w=32)
#define BDIM 16
#define HDIM 32
#define WDIM 32
#define TDIM (HDIM * WDIM)          // 1024
#define CDIM 768
#define MROWS (BDIM * TDIM)         // 16384
#define QC (CDIM / 4)               // 192

#define NELEM ((size_t)MROWS * CDIM)   // 12,582,912

// WKV chunked-scan config
#define LANES (BDIM * CDIM)         // 12288
#define NCH 16
#define CHL (TDIM / NCH)            // 64

// ---------------------------------------------------------------------------
// Scratch (device globals; no allocation allowed)
// ---------------------------------------------------------------------------
__device__ __nv_bfloat16 g_ah[4][NELEM];   // 0=xk 1=xv 2=xr 3=z
__device__ __nv_bfloat16 g_al[4][NELEM];
__device__ __nv_bfloat16 g_wh[4][CDIM * CDIM];  // W^T [N][K]
__device__ __nv_bfloat16 g_wl[4][CDIM * CDIM];
__device__ float g_k [NELEM];
__device__ float g_v [NELEM];
__device__ float g_sr[NELEM];
__device__ float g_y [NELEM];
// wkv chunk-local states and per-chunk initial states
__device__ float g_cp[NCH * LANES], g_cq[NCH * LANES], g_co[NCH * LANES];
__device__ float g_ip[NCH * LANES], g_iq[NCH * LANES], g_io[NCH * LANES];

// ---------------------------------------------------------------------------
// PTX helpers (base sm_103-compatible: mma.sync / ldmatrix / cp.async)
// ---------------------------------------------------------------------------
__device__ __forceinline__ uint32_t smem_u32(const void* p) {
    uint32_t a;
    asm("{ .reg .u64 t; cvta.to.shared.u64 t, %1; cvt.u32.u64 %0, t; }"
        : "=r"(a) : "l"(p));
    return a;
}

__device__ __forceinline__ void ldsm4(uint32_t& r0, uint32_t& r1,
                                      uint32_t& r2, uint32_t& r3, uint32_t addr) {
    asm volatile("ldmatrix.sync.aligned.m8n8.x4.shared.b16 {%0,%1,%2,%3}, [%4];"
                 : "=r"(r0), "=r"(r1), "=r"(r2), "=r"(r3) : "r"(addr));
}

__device__ __forceinline__ void mma16816(float* c, const uint32_t* a, const uint32_t* b) {
    asm volatile(
        "mma.sync.aligned.m16n8k16.row.col.f32.bf16.bf16.f32 "
        "{%0,%1,%2,%3}, {%4,%5,%6,%7}, {%8,%9}, {%0,%1,%2,%3};"
        : "+f"(c[0]), "+f"(c[1]), "+f"(c[2]), "+f"(c[3])
        : "r"(a[0]), "r"(a[1]), "r"(a[2]), "r"(a[3]), "r"(b[0]), "r"(b[1]));
}

__device__ __forceinline__ void cp16(uint32_t saddr, const void* gptr) {
    asm volatile("cp.async.cg.shared.global [%0], [%1], 16;"
                 :: "r"(saddr), "l"(gptr));
}
#define CP_COMMIT() asm volatile("cp.async.commit_group;" ::: "memory")
#define CP_WAIT1()  asm volatile("cp.async.wait_group 1;" ::: "memory")

// ---------------------------------------------------------------------------
// Stage 0: weight transpose + bf16 hi/lo split:  Wt[n][k] = W[k][n]
// ---------------------------------------------------------------------------
__global__ void wtrans_kernel(const float* __restrict__ W0, const float* __restrict__ W1,
                              const float* __restrict__ W2, const float* __restrict__ W3) {
    __shared__ float s[32][33];
    const float* W = (blockIdx.z == 0) ? W0 : (blockIdx.z == 1) ? W1
                   : (blockIdx.z == 2) ? W2 : W3;
    int n0 = blockIdx.x * 32, k0 = blockIdx.y * 32;
    int tx = threadIdx.x, ty = threadIdx.y;   // 32 x 8
#pragma unroll
    for (int i = 0; i < 4; i++) {
        int kk = ty + i * 8;
        s[kk][tx] = W[(size_t)(k0 + kk) * CDIM + n0 + tx];
    }
    __syncthreads();
#pragma unroll
    for (int i = 0; i < 4; i++) {
        int nn = ty + i * 8;
        float v = s[tx][nn];                  // = W[k0+tx][n0+nn]
        size_t o = (size_t)(n0 + nn) * CDIM + k0 + tx;
        __nv_bfloat16 h = __float2bfloat16(v);
        g_wh[blockIdx.z][o] = h;
        g_wl[blockIdx.z][o] = __float2bfloat16(v - __bfloat162float(h));
    }
}

// ---------------------------------------------------------------------------
// Stage 1: q_shift + token mixes -> bf16 hi/lo (xk, xv, xr), float4 vectorized
// ---------------------------------------------------------------------------
union BF4 { __nv_bfloat16 b[4]; uint2 u; };

__device__ __forceinline__ void store_hl4(int sel, size_t base, float4 v) {
    BF4 hi, lo;
    float vv[4] = {v.x, v.y, v.z, v.w};
#pragma unroll
    for (int j = 0; j < 4; j++) {
        __nv_bfloat16 h = __float2bfloat16(vv[j]);
        hi.b[j] = h;
        lo.b[j] = __float2bfloat16(vv[j] - __bfloat162float(h));
    }
    *(uint2*)(&g_ah[sel][base]) = hi.u;
    *(uint2*)(&g_al[sel][base]) = lo.u;
}

__global__ void shift_mix_kernel(const float* __restrict__ x,
                                 const float* __restrict__ mix_k,
                                 const float* __restrict__ mix_v,
                                 const float* __restrict__ mix_r) {
    int idx4 = blockIdx.x * blockDim.x + threadIdx.x;
    if (idx4 >= (int)(NELEM / 4)) return;
    int cq = idx4 % (CDIM / 4);
    int sp = idx4 / (CDIM / 4);
    int c  = cq * 4;
    size_t base = (size_t)sp * CDIM + c;
    int wq = sp % WDIM;
    int hq = (sp / WDIM) % HDIM;

    float4 xx = make_float4(0.f, 0.f, 0.f, 0.f);
    int g = c / QC;
    if (g == 0) {
        if (wq > 0)         xx = *(const float4*)(x + base - CDIM);
    } else if (g == 1) {
        if (wq < WDIM - 1)  xx = *(const float4*)(x + base + CDIM);
    } else if (g == 2) {
        if (hq > 0)         xx = *(const float4*)(x + base - (size_t)WDIM * CDIM);
    } else {
        if (hq < HDIM - 1)  xx = *(const float4*)(x + base + (size_t)WDIM * CDIM);
    }

    float4 xc = *(const float4*)(x + base);
    float4 mk = *(const float4*)(mix_k + c);
    float4 mv = *(const float4*)(mix_v + c);
    float4 mr = *(const float4*)(mix_r + c);

    float4 vk, vv, vr;
    vk.x = xc.x * mk.x + xx.x * (1.f - mk.x);
    vk.y = xc.y * mk.y + xx.y * (1.f - mk.y);
    vk.z = xc.z * mk.z + xx.z * (1.f - mk.z);
    vk.w = xc.w * mk.w + xx.w * (1.f - mk.w);
    vv.x = xc.x * mv.x + xx.x * (1.f - mv.x);
    vv.y = xc.y * mv.y + xx.y * (1.f - mv.y);
    vv.z = xc.z * mv.z + xx.z * (1.f - mv.z);
    vv.w = xc.w * mv.w + xx.w * (1.f - mv.w);
    vr.x = xc.x * mr.x + xx.x * (1.f - mr.x);
    vr.y = xc.y * mr.y + xx.y * (1.f - mr.y);
    vr.z = xc.z * mr.z + xx.z * (1.f - mr.z);
    vr.w = xc.w * mr.w + xx.w * (1.f - mr.w);

    store_hl4(0, base, vk);
    store_hl4(1, base, vv);
    store_hl4(2, base, vr);
}

// ---------------------------------------------------------------------------
// Stage 2/5: bf16 tensor-core GEMM via mma.sync (3-pass hi/lo split).
// CTA tile 128x128, 8 warps (2x4 -> 64x32 each), BK=32, 2-stage cp.async,
// 2 CTAs/SM.  aSel < 0: use blockIdx.z (0..2), act = (z==2).
// ---------------------------------------------------------------------------
#define PITCH 80
#define TILEB (128 * PITCH)               // 10240
#define STAGEB (4 * TILEB)                // 40960: [Ah | Al | Bh | Bl]
#define NSTAGE 2
#define SM_GEMM (NSTAGE * STAGEB)         // 81920

__global__ __launch_bounds__(256, 2)
void tc_gemm_kernel(int aSel, float* __restrict__ cOut) {
    extern __shared__ char smem[];
    const uint32_t sb = smem_u32(smem);
    const int tid = threadIdx.x;
    const int w = tid >> 5, l = tid & 31;
    const int wm = w >> 2, wn = w & 3;

    const int s = (aSel < 0) ? (int)blockIdx.z : aSel;
    const int act = (aSel < 0) ? (s == 2 ? 1 : 0) : 0;

    const __nv_bfloat16* __restrict__ Ah = g_ah[s];
    const __nv_bfloat16* __restrict__ Al = g_al[s];
    const __nv_bfloat16* __restrict__ Wh = g_wh[s];
    const __nv_bfloat16* __restrict__ Wl = g_wl[s];
    float* __restrict__ C = (s == 0) ? g_k : (s == 1) ? g_v
                          : (s == 2) ? g_sr : cOut;

    const int mrow0 = blockIdx.y * 128;
    const int ncol0 = blockIdx.x * 128;

    float acc[4][4][4];
#pragma unroll
    for (int i = 0; i < 4; i++)
#pragma unroll
        for (int j = 0; j < 4; j++)
#pragma unroll
            for (int q = 0; q < 4; q++) acc[i][j][q] = 0.0f;

    auto issue = [&](int kc, int st) {
        if (kc < 24) {
            uint32_t s0 = sb + st * STAGEB;
#pragma unroll
            for (int j = 0; j < 2; j++) {
                int id = tid + j * 256;          // 0..511
                int row = id >> 2, cc = id & 3;
                size_t gA = (size_t)(mrow0 + row) * CDIM + kc * 32 + cc * 8;
                size_t gB = (size_t)(ncol0 + row) * CDIM + kc * 32 + cc * 8;
                uint32_t so = (uint32_t)(row * PITCH + cc * 16);
                cp16(s0 + 0 * TILEB + so, Ah + gA);
                cp16(s0 + 1 * TILEB + so, Al + gA);
                cp16(s0 + 2 * TILEB + so, Wh + gB);
                cp16(s0 + 3 * TILEB + so, Wl + gB);
            }
        }
        CP_COMMIT();
    };

    issue(0, 0); issue(1, 1);

    const uint32_t aOff = (uint32_t)((wm * 64 + (l & 15)) * PITCH + (l >> 4) * 16);
    const uint32_t bOff = (uint32_t)(2 * TILEB +
                    (wn * 32 + ((l & 7) | ((l >> 4) << 3))) * PITCH + ((l >> 3) & 1) * 16);

    for (int kc = 0; kc < 24; kc++) {
        int st = kc & 1;
        CP_WAIT1();
        __syncthreads();
        uint32_t s0 = sb + st * STAGEB;
#pragma unroll
        for (int ks = 0; ks < 2; ks++) {
            uint32_t ah[4][4], al[4][4], bh[2][4], bl[2][4];
            uint32_t aA = s0 + aOff + ks * 32;
            uint32_t bA = s0 + bOff + ks * 32;
#pragma unroll
            for (int am = 0; am < 4; am++) {
                ldsm4(ah[am][0], ah[am][1], ah[am][2], ah[am][3],
                      aA + am * 16 * PITCH);
                ldsm4(al[am][0], al[am][1], al[am][2], al[am][3],
                      aA + am * 16 * PITCH + TILEB);
            }
#pragma unroll
            for (int bn = 0; bn < 2; bn++) {
                ldsm4(bh[bn][0], bh[bn][1], bh[bn][2], bh[bn][3],
                      bA + bn * 16 * PITCH);
                ldsm4(bl[bn][0], bl[bn][1], bl[bn][2], bl[bn][3],
                      bA + bn * 16 * PITCH + TILEB);
            }
#pragma unroll
            for (int am = 0; am < 4; am++)
#pragma unroll
                for (int an = 0; an < 4; an++) {
                    const uint32_t* bhp = &bh[an >> 1][(an & 1) * 2];
                    const uint32_t* blp = &bl[an >> 1][(an & 1) * 2];
                    mma16816(acc[am][an], ah[am], bhp);
                    mma16816(acc[am][an], ah[am], blp);
                    mma16816(acc[am][an], al[am], bhp);
                }
        }
        __syncthreads();
        issue(kc + NSTAGE, st);
    }

#pragma unroll
    for (int am = 0; am < 4; am++) {
        int r0 = mrow0 + wm * 64 + am * 16 + (l >> 2);
#pragma unroll
        for (int an = 0; an < 4; an++) {
            int cc = ncol0 + wn * 32 + an * 8 + (l & 3) * 2;
            float v0 = acc[am][an][0], v1 = acc[am][an][1];
            float v2 = acc[am][an][2], v3 = acc[am][an][3];
            if (act == 1) {
                v0 = 1.0f / (1.0f + __expf(-v0));
                v1 = 1.0f / (1.0f + __expf(-v1));
                v2 = 1.0f / (1.0f + __expf(-v2));
                v3 = 1.0f / (1.0f + __expf(-v3));
            }
            *(float2*)(C + (size_t)r0 * CDIM + cc)       = make_float2(v0, v1);
            *(float2*)(C + (size_t)(r0 + 8) * CDIM + cc) = make_float2(v2, v3);
        }
    }
}

// ---------------------------------------------------------------------------
// Stage 3: WKV as 3-phase chunked scan (16 chunks of 64 steps)
// state (p, q, o); unnormalized: p~ = p e^o obeys p~_t = e^w p~_{t-1} + v e^k
// ---------------------------------------------------------------------------
__device__ __forceinline__ void wkv_update(float& p, float& q, float& o,
                                           float w, float kt, float vt) {
    float wo  = w + o;
    float no2 = fmaxf(wo, kt);
    float A2  = __expf(wo - no2);
    float B2  = __expf(kt - no2);
    p = A2 * p + B2 * vt;
    q = A2 * q + B2;
    o = no2;
}

__global__ void wkv_p1_kernel(const float* __restrict__ spatial_decay) {
    int idx = blockIdx.x * blockDim.x + threadIdx.x;   // 0..NCH*LANES-1
    if (idx >= NCH * LANES) return;
    int chunk = idx / LANES;
    int lane  = idx % LANES;
    int c = lane % CDIM, b = lane / CDIM;
    float w = spatial_decay[c] * (1.0f / (float)TDIM);

    const float* kp = g_k + ((size_t)b * TDIM + chunk * CHL) * CDIM + c;
    const float* vp = g_v + ((size_t)b * TDIM + chunk * CHL) * CDIM + c;

    float p = 0.f, q = 0.f, o = -1e38f;
#pragma unroll 4
    for (int t = 0; t < CHL; t++)
        wkv_update(p, q, o, w, kp[(size_t)t * CDIM], vp[(size_t)t * CDIM]);

    g_cp[idx] = p; g_cq[idx] = q; g_co[idx] = o;
}

__global__ void wkv_p2_kernel(const float* __restrict__ spatial_decay) {
    int lane = blockIdx.x * blockDim.x + threadIdx.x;
    if (lane >= LANES) return;
    int c = lane % CDIM;
    float wL = spatial_decay[c] * (1.0f / (float)TDIM) * (float)CHL;

    float p = 0.f, q = 0.f, o = -1e38f;
#pragma unroll
    for (int j = 0; j < NCH; j++) {
        int idx = j * LANES + lane;
        g_ip[idx] = p; g_iq[idx] = q; g_io[idx] = o;
        float cp = g_cp[idx], cq = g_cq[idx], co = g_co[idx];
        float ow = o + wL;
        float no = fmaxf(ow, co);
        float A = __expf(ow - no);
        float B = __expf(co - no);
        p = A * p + B * cp;
        q = A * q + B * cq;
        o = no;
    }
}

__global__ void wkv_p3_kernel(const float* __restrict__ spatial_decay,
                              const float* __restrict__ spatial_first) {
    int idx = blockIdx.x * blockDim.x + threadIdx.x;
    if (idx >= NCH * LANES) return;
    int chunk = idx / LANES;
    int lane  = idx % LANES;
    int c = lane % CDIM, b = lane / CDIM;
    float w = spatial_decay[c] * (1.0f / (float)TDIM);
    float u = spatial_first[c] * (1.0f / (float)TDIM);

    const float* kp = g_k + ((size_t)b * TDIM + chunk * CHL) * CDIM + c;
    const float* vp = g_v + ((size_t)b * TDIM + chunk * CHL) * CDIM + c;
    float*       yp = g_y + ((size_t)b * TDIM + chunk * CHL) * CDIM + c;

    float p = g_ip[idx], q = g_iq[idx], o = g_io[idx];
#pragma unroll 4
    for (int t = 0; t < CHL; t++) {
        float kt = kp[(size_t)t * CDIM];
        float vt = vp[(size_t)t * CDIM];
        float uk = u + kt;
        float no = fmaxf(o, uk);
        float Aa = __expf(o - no);
        float Bb = __expf(uk - no);
        yp[(size_t)t * CDIM] = __fdividef(Aa * p + Bb * vt, Aa * q + Bb);
        wkv_update(p, q, o, w, kt, vt);
    }
}

// ---------------------------------------------------------------------------
// Stage 4: layernorm(y) * sigmoid_r -> z (bf16 hi/lo). 192 threads/row.
// ---------------------------------------------------------------------------
__device__ __forceinline__ float block_reduce_sum6(float val) {
    __shared__ float sh[6];
    __shared__ float total;
    int lane = threadIdx.x & 31;
    int wid  = threadIdx.x >> 5;     // 0..5
    __syncthreads();
#pragma unroll
    for (int off = 16; off > 0; off >>= 1)
        val += __shfl_xor_sync(0xffffffffu, val, off);
    if (lane == 0) sh[wid] = val;
    __syncthreads();
    if (wid == 0) {
        float v2 = (lane < 6) ? sh[lane] : 0.0f;
#pragma unroll
        for (int off = 4; off > 0; off >>= 1)
            v2 += __shfl_xor_sync(0xffffffffu, v2, off);
        if (lane == 0) total = v2;
    }
    __syncthreads();
    return total;
}

__global__ void ln_gate_kernel(const float* __restrict__ ln_g,
                               const float* __restrict__ ln_b) {
    int row = blockIdx.x;
    int tid = threadIdx.x;                   // 192 threads x 4 elems
    size_t base = (size_t)row * CDIM + tid * 4;

    float4 y4  = *(const float4*)(g_y  + base);
    float s = y4.x + y4.y + y4.z + y4.w;
    s = block_reduce_sum6(s);
    float mu = s * (1.0f / CDIM);

    float d0 = y4.x - mu, d1 = y4.y - mu, d2 = y4.z - mu, d3 = y4.w - mu;
    float ss = d0 * d0 + d1 * d1 + d2 * d2 + d3 * d3;
    ss = block_reduce_sum6(ss);
    float rstd = rsqrtf(ss * (1.0f / CDIM) + 1e-5f);

    float4 sr4 = *(const float4*)(g_sr + base);
    float4 g4  = *(const float4*)(ln_g + tid * 4);
    float4 b4  = *(const float4*)(ln_b + tid * 4);
    float4 z;
    z.x = sr4.x * (d0 * rstd * g4.x + b4.x);
    z.y = sr4.y * (d1 * rstd * g4.y + b4.y);
    z.z = sr4.z * (d2 * rstd * g4.z + b4.z);
    z.w = sr4.w * (d3 * rstd * g4.w + b4.w);
    store_hl4(3, base, z);
}

// ---------------------------------------------------------------------------
// Launch
// ---------------------------------------------------------------------------
extern "C" void kernel_launch(void* const* d_in, const int* in_sizes, int n_in,
                              void* d_out, int out_size) {
    const float* x   = (const float*)d_in[0];
    const float* sd  = (const float*)d_in[3];
    const float* sf  = (const float*)d_in[4];
    const float* mk  = (const float*)d_in[5];
    const float* mv  = (const float*)d_in[6];
    const float* mr  = (const float*)d_in[7];
    const float* Wk  = (const float*)d_in[8];
    const float* Wv  = (const float*)d_in[9];
    const float* Wr  = (const float*)d_in[10];
    const float* Wo  = (const float*)d_in[11];
    const float* lg  = (const float*)d_in[12];
    const float* lb  = (const float*)d_in[13];
    float* out = (float*)d_out;

    cudaFuncSetAttribute(tc_gemm_kernel,
                         cudaFuncAttributeMaxDynamicSharedMemorySize, SM_GEMM);

    // 0. transpose + split weights
    {
        dim3 blk(32, 8);
        dim3 grd(CDIM / 32, CDIM / 32, 4);
        wtrans_kernel<<<grd, blk>>>(Wk, Wv, Wr, Wo);
    }

    // 1. q_shift + mixes -> bf16 hi/lo (vectorized x4)
    {
        int n4 = (int)(NELEM / 4);
        shift_mix_kernel<<<(n4 + 255) / 256, 256>>>(x, mk, mv, mr);
    }

    // 2. fused k / v / sr GEMMs (z = 0,1,2)
    {
        dim3 gg(CDIM / 128, MROWS / 128, 3);
        tc_gemm_kernel<<<gg, 256, SM_GEMM>>>(-1, nullptr);
    }

    // 3. WKV chunked scan
    wkv_p1_kernel<<<(NCH * LANES) / 256, 256>>>(sd);
    wkv_p2_kernel<<<(LANES + 255) / 256, 256>>>(sd);
    wkv_p3_kernel<<<(NCH * LANES) / 256, 256>>>(sd, sf);

    // 4. layernorm + gate -> z (bf16 hi/lo)
    ln_gate_kernel<<<MROWS, 192>>>(lg, lb);

    // 5. output projection -> d_out
    {
        dim3 gg(CDIM / 128, MROWS / 128, 1);
        tc_gemm_kernel<<<gg, 256, SM_GEMM>>>(3, out);
    }
}

// round 5
// speedup vs baseline: 4.9726x; 1.4279x over previous
#include <cuda_runtime.h>
#include <cuda_fp16.h>
#include <stdint.h>
#include <math.h>

// Problem constants (fixed by dataset: x is (16, 1024, 768), h=w=32)
#define BDIM 16
#define HDIM 32
#define WDIM 32
#define TDIM (HDIM * WDIM)          // 1024
#define CDIM 768
#define MROWS (BDIM * TDIM)         // 16384
#define QC (CDIM / 4)               // 192

#define NELEM ((size_t)MROWS * CDIM)   // 12,582,912

// WKV chunked-scan config
#define LANES (BDIM * CDIM)         // 12288
#define NCH 16
#define CHL (TDIM / NCH)            // 64

// ---------------------------------------------------------------------------
// Scratch (device globals; no allocation allowed)
// ---------------------------------------------------------------------------
__device__ __half g_a16[4][NELEM];              // 0=xk 1=xv 2=xr 3=z (fp16)
__device__ __half g_wh[4][CDIM * CDIM];         // W^T [N][K] fp16 hi
__device__ __half g_wl[4][CDIM * CDIM];         // W^T [N][K] fp16 lo
__device__ float g_k [NELEM];
__device__ float g_v [NELEM];
__device__ float g_sr[NELEM];
__device__ float g_y [NELEM];
// wkv chunk-local states and per-chunk initial states
__device__ float g_cp[NCH * LANES], g_cq[NCH * LANES], g_co[NCH * LANES];
__device__ float g_ip[NCH * LANES], g_iq[NCH * LANES], g_io[NCH * LANES];

// ---------------------------------------------------------------------------
// PTX helpers (base sm_103-compatible: mma.sync / ldmatrix / cp.async)
// ---------------------------------------------------------------------------
__device__ __forceinline__ uint32_t smem_u32(const void* p) {
    uint32_t a;
    asm("{ .reg .u64 t; cvta.to.shared.u64 t, %1; cvt.u32.u64 %0, t; }"
        : "=r"(a) : "l"(p));
    return a;
}

__device__ __forceinline__ void ldsm4(uint32_t& r0, uint32_t& r1,
                                      uint32_t& r2, uint32_t& r3, uint32_t addr) {
    asm volatile("ldmatrix.sync.aligned.m8n8.x4.shared.b16 {%0,%1,%2,%3}, [%4];"
                 : "=r"(r0), "=r"(r1), "=r"(r2), "=r"(r3) : "r"(addr));
}

__device__ __forceinline__ void mma16816(float* c, const uint32_t* a, const uint32_t* b) {
    asm volatile(
        "mma.sync.aligned.m16n8k16.row.col.f32.f16.f16.f32 "
        "{%0,%1,%2,%3}, {%4,%5,%6,%7}, {%8,%9}, {%0,%1,%2,%3};"
        : "+f"(c[0]), "+f"(c[1]), "+f"(c[2]), "+f"(c[3])
        : "r"(a[0]), "r"(a[1]), "r"(a[2]), "r"(a[3]), "r"(b[0]), "r"(b[1]));
}

__device__ __forceinline__ void cp16(uint32_t saddr, const void* gptr) {
    asm volatile("cp.async.cg.shared.global [%0], [%1], 16;"
                 :: "r"(saddr), "l"(gptr));
}
#define CP_COMMIT() asm volatile("cp.async.commit_group;" ::: "memory")
#define CP_WAIT2()  asm volatile("cp.async.wait_group 2;" ::: "memory")

// ---------------------------------------------------------------------------
// Stage 0: weight transpose + fp16 hi/lo split:  Wt[n][k] = W[k][n]
// ---------------------------------------------------------------------------
__global__ void wtrans_kernel(const float* __restrict__ W0, const float* __restrict__ W1,
                              const float* __restrict__ W2, const float* __restrict__ W3) {
    __shared__ float s[32][33];
    const float* W = (blockIdx.z == 0) ? W0 : (blockIdx.z == 1) ? W1
                   : (blockIdx.z == 2) ? W2 : W3;
    int n0 = blockIdx.x * 32, k0 = blockIdx.y * 32;
    int tx = threadIdx.x, ty = threadIdx.y;   // 32 x 8
#pragma unroll
    for (int i = 0; i < 4; i++) {
        int kk = ty + i * 8;
        s[kk][tx] = W[(size_t)(k0 + kk) * CDIM + n0 + tx];
    }
    __syncthreads();
#pragma unroll
    for (int i = 0; i < 4; i++) {
        int nn = ty + i * 8;
        float v = s[tx][nn];                  // = W[k0+tx][n0+nn]
        size_t o = (size_t)(n0 + nn) * CDIM + k0 + tx;
        __half h = __float2half(v);
        g_wh[blockIdx.z][o] = h;
        g_wl[blockIdx.z][o] = __float2half(v - __half2float(h));
    }
}

// ---------------------------------------------------------------------------
// Stage 1: q_shift + token mixes -> fp16 (xk, xv, xr), float4 vectorized
// ---------------------------------------------------------------------------
union H4 { __half h[4]; uint2 u; };

__device__ __forceinline__ void store_h4(int sel, size_t base, float4 v) {
    H4 o;
    o.h[0] = __float2half(v.x);
    o.h[1] = __float2half(v.y);
    o.h[2] = __float2half(v.z);
    o.h[3] = __float2half(v.w);
    *(uint2*)(&g_a16[sel][base]) = o.u;
}

__global__ void shift_mix_kernel(const float* __restrict__ x,
                                 const float* __restrict__ mix_k,
                                 const float* __restrict__ mix_v,
                                 const float* __restrict__ mix_r) {
    int idx4 = blockIdx.x * blockDim.x + threadIdx.x;
    if (idx4 >= (int)(NELEM / 4)) return;
    int cq = idx4 % (CDIM / 4);
    int sp = idx4 / (CDIM / 4);
    int c  = cq * 4;
    size_t base = (size_t)sp * CDIM + c;
    int wq = sp % WDIM;
    int hq = (sp / WDIM) % HDIM;

    float4 xx = make_float4(0.f, 0.f, 0.f, 0.f);
    int g = c / QC;
    if (g == 0) {
        if (wq > 0)         xx = *(const float4*)(x + base - CDIM);
    } else if (g == 1) {
        if (wq < WDIM - 1)  xx = *(const float4*)(x + base + CDIM);
    } else if (g == 2) {
        if (hq > 0)         xx = *(const float4*)(x + base - (size_t)WDIM * CDIM);
    } else {
        if (hq < HDIM - 1)  xx = *(const float4*)(x + base + (size_t)WDIM * CDIM);
    }

    float4 xc = *(const float4*)(x + base);
    float4 mk = *(const float4*)(mix_k + c);
    float4 mv = *(const float4*)(mix_v + c);
    float4 mr = *(const float4*)(mix_r + c);

    float4 vk, vv, vr;
    vk.x = xc.x * mk.x + xx.x * (1.f - mk.x);
    vk.y = xc.y * mk.y + xx.y * (1.f - mk.y);
    vk.z = xc.z * mk.z + xx.z * (1.f - mk.z);
    vk.w = xc.w * mk.w + xx.w * (1.f - mk.w);
    vv.x = xc.x * mv.x + xx.x * (1.f - mv.x);
    vv.y = xc.y * mv.y + xx.y * (1.f - mv.y);
    vv.z = xc.z * mv.z + xx.z * (1.f - mv.z);
    vv.w = xc.w * mv.w + xx.w * (1.f - mv.w);
    vr.x = xc.x * mr.x + xx.x * (1.f - mr.x);
    vr.y = xc.y * mr.y + xx.y * (1.f - mr.y);
    vr.z = xc.z * mr.z + xx.z * (1.f - mr.z);
    vr.w = xc.w * mr.w + xx.w * (1.f - mr.w);

    store_h4(0, base, vk);
    store_h4(1, base, vv);
    store_h4(2, base, vr);
}

// ---------------------------------------------------------------------------
// Stage 2/5: fp16 tensor-core GEMM via mma.sync (2-pass W hi/lo split).
// C[M,N] = A[M,K] @ W[K,N].  CTA tile 128x128, 8 warps (2x4 -> 64x32 each),
// BK=32, 3-stage cp.async, 2 CTAs/SM.  aSel < 0: blockIdx.z selects 0..2.
// ---------------------------------------------------------------------------
#define PITCH 80
#define TILEB (128 * PITCH)               // 10240
#define STAGEB (3 * TILEB)                // 30720: [A | Wh | Wl]
#define NSTAGE 3
#define SM_GEMM (NSTAGE * STAGEB)         // 92160

__global__ __launch_bounds__(256, 2)
void tc_gemm_kernel(int aSel, float* __restrict__ cOut) {
    extern __shared__ char smem[];
    const uint32_t sb = smem_u32(smem);
    const int tid = threadIdx.x;
    const int w = tid >> 5, l = tid & 31;
    const int wm = w >> 2, wn = w & 3;

    const int s = (aSel < 0) ? (int)blockIdx.z : aSel;
    const int act = (aSel < 0) ? (s == 2 ? 1 : 0) : 0;

    const __half* __restrict__ A  = g_a16[s];
    const __half* __restrict__ Wh = g_wh[s];
    const __half* __restrict__ Wl = g_wl[s];
    float* __restrict__ C = (s == 0) ? g_k : (s == 1) ? g_v
                          : (s == 2) ? g_sr : cOut;

    const int mrow0 = blockIdx.y * 128;
    const int ncol0 = blockIdx.x * 128;

    float acc[4][4][4];
#pragma unroll
    for (int i = 0; i < 4; i++)
#pragma unroll
        for (int j = 0; j < 4; j++)
#pragma unroll
            for (int q = 0; q < 4; q++) acc[i][j][q] = 0.0f;

    auto issue = [&](int kc, int st) {
        if (kc < 24) {
            uint32_t s0 = sb + st * STAGEB;
#pragma unroll
            for (int j = 0; j < 2; j++) {
                int id = tid + j * 256;          // 0..511
                int row = id >> 2, cc = id & 3;
                size_t gA = (size_t)(mrow0 + row) * CDIM + kc * 32 + cc * 8;
                size_t gB = (size_t)(ncol0 + row) * CDIM + kc * 32 + cc * 8;
                uint32_t so = (uint32_t)(row * PITCH + cc * 16);
                cp16(s0 + 0 * TILEB + so, A  + gA);
                cp16(s0 + 1 * TILEB + so, Wh + gB);
                cp16(s0 + 2 * TILEB + so, Wl + gB);
            }
        }
        CP_COMMIT();
    };

    issue(0, 0); issue(1, 1); issue(2, 2);

    const uint32_t aOff = (uint32_t)((wm * 64 + (l & 15)) * PITCH + (l >> 4) * 16);
    const uint32_t bOff = (uint32_t)(1 * TILEB +
                    (wn * 32 + ((l & 7) | ((l >> 4) << 3))) * PITCH + ((l >> 3) & 1) * 16);

    int st = 0;
    for (int kc = 0; kc < 24; kc++) {
        CP_WAIT2();
        __syncthreads();
        uint32_t s0 = sb + st * STAGEB;
#pragma unroll
        for (int ks = 0; ks < 2; ks++) {
            uint32_t a[4][4], bh[2][4], bl[2][4];
            uint32_t aA = s0 + aOff + ks * 32;
            uint32_t bA = s0 + bOff + ks * 32;
#pragma unroll
            for (int am = 0; am < 4; am++)
                ldsm4(a[am][0], a[am][1], a[am][2], a[am][3],
                      aA + am * 16 * PITCH);
#pragma unroll
            for (int bn = 0; bn < 2; bn++) {
                ldsm4(bh[bn][0], bh[bn][1], bh[bn][2], bh[bn][3],
                      bA + bn * 16 * PITCH);
                ldsm4(bl[bn][0], bl[bn][1], bl[bn][2], bl[bn][3],
                      bA + bn * 16 * PITCH + TILEB);
            }
#pragma unroll
            for (int am = 0; am < 4; am++)
#pragma unroll
                for (int an = 0; an < 4; an++) {
                    const uint32_t* bhp = &bh[an >> 1][(an & 1) * 2];
                    const uint32_t* blp = &bl[an >> 1][(an & 1) * 2];
                    mma16816(acc[am][an], a[am], bhp);
                    mma16816(acc[am][an], a[am], blp);
                }
        }
        __syncthreads();
        issue(kc + NSTAGE, st);
        st = (st == NSTAGE - 1) ? 0 : st + 1;
    }

#pragma unroll
    for (int am = 0; am < 4; am++) {
        int r0 = mrow0 + wm * 64 + am * 16 + (l >> 2);
#pragma unroll
        for (int an = 0; an < 4; an++) {
            int cc = ncol0 + wn * 32 + an * 8 + (l & 3) * 2;
            float v0 = acc[am][an][0], v1 = acc[am][an][1];
            float v2 = acc[am][an][2], v3 = acc[am][an][3];
            if (act == 1) {
                v0 = 1.0f / (1.0f + __expf(-v0));
                v1 = 1.0f / (1.0f + __expf(-v1));
                v2 = 1.0f / (1.0f + __expf(-v2));
                v3 = 1.0f / (1.0f + __expf(-v3));
            }
            *(float2*)(C + (size_t)r0 * CDIM + cc)       = make_float2(v0, v1);
            *(float2*)(C + (size_t)(r0 + 8) * CDIM + cc) = make_float2(v2, v3);
        }
    }
}

// ---------------------------------------------------------------------------
// Stage 3: WKV as 3-phase chunked scan (16 chunks of 64 steps)
// ---------------------------------------------------------------------------
__device__ __forceinline__ void wkv_update(float& p, float& q, float& o,
                                           float w, float kt, float vt) {
    float wo  = w + o;
    float no2 = fmaxf(wo, kt);
    float A2  = __expf(wo - no2);
    float B2  = __expf(kt - no2);
    p = A2 * p + B2 * vt;
    q = A2 * q + B2;
    o = no2;
}

__global__ void wkv_p1_kernel(const float* __restrict__ spatial_decay) {
    int idx = blockIdx.x * blockDim.x + threadIdx.x;   // 0..NCH*LANES-1
    if (idx >= NCH * LANES) return;
    int chunk = idx / LANES;
    int lane  = idx % LANES;
    int c = lane % CDIM, b = lane / CDIM;
    float w = spatial_decay[c] * (1.0f / (float)TDIM);

    const float* kp = g_k + ((size_t)b * TDIM + chunk * CHL) * CDIM + c;
    const float* vp = g_v + ((size_t)b * TDIM + chunk * CHL) * CDIM + c;

    float p = 0.f, q = 0.f, o = -1e38f;
#pragma unroll 4
    for (int t = 0; t < CHL; t++)
        wkv_update(p, q, o, w, kp[(size_t)t * CDIM], vp[(size_t)t * CDIM]);

    g_cp[idx] = p; g_cq[idx] = q; g_co[idx] = o;
}

__global__ void wkv_p2_kernel(const float* __restrict__ spatial_decay) {
    int lane = blockIdx.x * blockDim.x + threadIdx.x;
    if (lane >= LANES) return;
    int c = lane % CDIM;
    float wL = spatial_decay[c] * (1.0f / (float)TDIM) * (float)CHL;

    float p = 0.f, q = 0.f, o = -1e38f;
#pragma unroll
    for (int j = 0; j < NCH; j++) {
        int idx = j * LANES + lane;
        g_ip[idx] = p; g_iq[idx] = q; g_io[idx] = o;
        float cp = g_cp[idx], cq = g_cq[idx], co = g_co[idx];
        float ow = o + wL;
        float no = fmaxf(ow, co);
        float A = __expf(ow - no);
        float B = __expf(co - no);
        p = A * p + B * cp;
        q = A * q + B * cq;
        o = no;
    }
}

__global__ void wkv_p3_kernel(const float* __restrict__ spatial_decay,
                              const float* __restrict__ spatial_first) {
    int idx = blockIdx.x * blockDim.x + threadIdx.x;
    if (idx >= NCH * LANES) return;
    int chunk = idx / LANES;
    int lane  = idx % LANES;
    int c = lane % CDIM, b = lane / CDIM;
    float w = spatial_decay[c] * (1.0f / (float)TDIM);
    float u = spatial_first[c] * (1.0f / (float)TDIM);

    const float* kp = g_k + ((size_t)b * TDIM + chunk * CHL) * CDIM + c;
    const float* vp = g_v + ((size_t)b * TDIM + chunk * CHL) * CDIM + c;
    float*       yp = g_y + ((size_t)b * TDIM + chunk * CHL) * CDIM + c;

    float p = g_ip[idx], q = g_iq[idx], o = g_io[idx];
#pragma unroll 4
    for (int t = 0; t < CHL; t++) {
        float kt = kp[(size_t)t * CDIM];
        float vt = vp[(size_t)t * CDIM];
        float uk = u + kt;
        float no = fmaxf(o, uk);
        float Aa = __expf(o - no);
        float Bb = __expf(uk - no);
        yp[(size_t)t * CDIM] = __fdividef(Aa * p + Bb * vt, Aa * q + Bb);
        wkv_update(p, q, o, w, kt, vt);
    }
}

// ---------------------------------------------------------------------------
// Stage 4: layernorm(y) * sigmoid_r -> z (fp16). Warp per row, 8 rows/block.
// ---------------------------------------------------------------------------
__global__ __launch_bounds__(256)
void ln_gate_kernel(const float* __restrict__ ln_g,
                    const float* __restrict__ ln_b) {
    int wid  = threadIdx.x >> 5;
    int lane = threadIdx.x & 31;
    int row  = blockIdx.x * 8 + wid;
    size_t rbase = (size_t)row * CDIM;

    // 6 float4 per lane: c = (i*32 + lane)*4
    float4 y4[6];
    float s = 0.f;
#pragma unroll
    for (int i = 0; i < 6; i++) {
        y4[i] = *(const float4*)(g_y + rbase + (size_t)(i * 32 + lane) * 4);
        s += y4[i].x + y4[i].y + y4[i].z + y4[i].w;
    }
#pragma unroll
    for (int off = 16; off > 0; off >>= 1)
        s += __shfl_xor_sync(0xffffffffu, s, off);
    float mu = s * (1.0f / CDIM);

    float ss = 0.f;
#pragma unroll
    for (int i = 0; i < 6; i++) {
        float d0 = y4[i].x - mu, d1 = y4[i].y - mu;
        float d2 = y4[i].z - mu, d3 = y4[i].w - mu;
        ss += d0 * d0 + d1 * d1 + d2 * d2 + d3 * d3;
    }
#pragma unroll
    for (int off = 16; off > 0; off >>= 1)
        ss += __shfl_xor_sync(0xffffffffu, ss, off);
    float rstd = rsqrtf(ss * (1.0f / CDIM) + 1e-5f);

#pragma unroll
    for (int i = 0; i < 6; i++) {
        int c = (i * 32 + lane) * 4;
        float4 sr4 = *(const float4*)(g_sr + rbase + c);
        float4 g4  = *(const float4*)(ln_g + c);
        float4 b4  = *(const float4*)(ln_b + c);
        float4 z;
        z.x = sr4.x * ((y4[i].x - mu) * rstd * g4.x + b4.x);
        z.y = sr4.y * ((y4[i].y - mu) * rstd * g4.y + b4.y);
        z.z = sr4.z * ((y4[i].z - mu) * rstd * g4.z + b4.z);
        z.w = sr4.w * ((y4[i].w - mu) * rstd * g4.w + b4.w);
        store_h4(3, rbase + c, z);
    }
}

// ---------------------------------------------------------------------------
// Launch
// ---------------------------------------------------------------------------
extern "C" void kernel_launch(void* const* d_in, const int* in_sizes, int n_in,
                              void* d_out, int out_size) {
    const float* x   = (const float*)d_in[0];
    const float* sd  = (const float*)d_in[3];
    const float* sf  = (const float*)d_in[4];
    const float* mk  = (const float*)d_in[5];
    const float* mv  = (const float*)d_in[6];
    const float* mr  = (const float*)d_in[7];
    const float* Wk  = (const float*)d_in[8];
    const float* Wv  = (const float*)d_in[9];
    const float* Wr  = (const float*)d_in[10];
    const float* Wo  = (const float*)d_in[11];
    const float* lg  = (const float*)d_in[12];
    const float* lb  = (const float*)d_in[13];
    float* out = (float*)d_out;

    cudaFuncSetAttribute(tc_gemm_kernel,
                         cudaFuncAttributeMaxDynamicSharedMemorySize, SM_GEMM);

    // 0. transpose + split weights (fp16 hi/lo)
    {
        dim3 blk(32, 8);
        dim3 grd(CDIM / 32, CDIM / 32, 4);
        wtrans_kernel<<<grd, blk>>>(Wk, Wv, Wr, Wo);
    }

    // 1. q_shift + mixes -> fp16
    {
        int n4 = (int)(NELEM / 4);
        shift_mix_kernel<<<(n4 + 255) / 256, 256>>>(x, mk, mv, mr);
    }

    // 2. fused k / v / sr GEMMs (z = 0,1,2)
    {
        dim3 gg(CDIM / 128, MROWS / 128, 3);
        tc_gemm_kernel<<<gg, 256, SM_GEMM>>>(-1, nullptr);
    }

    // 3. WKV chunked scan
    wkv_p1_kernel<<<(NCH * LANES) / 256, 256>>>(sd);
    wkv_p2_kernel<<<(LANES + 255) / 256, 256>>>(sd);
    wkv_p3_kernel<<<(NCH * LANES) / 256, 256>>>(sd, sf);

    // 4. layernorm + gate -> z (fp16)
    ln_gate_kernel<<<MROWS / 8, 256>>>(lg, lb);

    // 5. output projection -> d_out
    {
        dim3 gg(CDIM / 128, MROWS / 128, 1);
        tc_gemm_kernel<<<gg, 256, SM_GEMM>>>(3, out);
    }
}

// round 6
// speedup vs baseline: 5.4904x; 1.1041x over previous
#include <cuda_runtime.h>
#include <cuda_fp16.h>
#include <stdint.h>
#include <math.h>

// Problem constants (fixed by dataset: x is (16, 1024, 768), h=w=32)
#define BDIM 16
#define HDIM 32
#define WDIM 32
#define TDIM (HDIM * WDIM)          // 1024
#define CDIM 768
#define MROWS (BDIM * TDIM)         // 16384
#define QC (CDIM / 4)               // 192

#define NELEM ((size_t)MROWS * CDIM)   // 12,582,912

// WKV chunked-scan config
#define LANES (BDIM * CDIM)         // 12288
#define NCH 32
#define CHL (TDIM / NCH)            // 32

// ---------------------------------------------------------------------------
// Scratch (device globals; no allocation allowed)
// ---------------------------------------------------------------------------
__device__ __half g_a16[4][NELEM];              // 0=xk 1=xv 2=xr 3=z (fp16)
__device__ __half g_wh[4][CDIM * CDIM];         // W^T [N][K] fp16 hi
__device__ __half g_wl[4][CDIM * CDIM];         // W^T [N][K] fp16 lo
__device__ __half g_k16[NELEM];
__device__ __half g_v16[NELEM];
__device__ float g_sr[NELEM];
__device__ float g_y [NELEM];
// wkv chunk-local states and per-chunk initial states
__device__ float g_cp[NCH * LANES], g_cq[NCH * LANES], g_co[NCH * LANES];
__device__ float g_ip[NCH * LANES], g_iq[NCH * LANES], g_io[NCH * LANES];

// ---------------------------------------------------------------------------
// PTX helpers (base sm_103-compatible: mma.sync / ldmatrix / cp.async)
// ---------------------------------------------------------------------------
__device__ __forceinline__ uint32_t smem_u32(const void* p) {
    uint32_t a;
    asm("{ .reg .u64 t; cvta.to.shared.u64 t, %1; cvt.u32.u64 %0, t; }"
        : "=r"(a) : "l"(p));
    return a;
}

__device__ __forceinline__ void ldsm4(uint32_t& r0, uint32_t& r1,
                                      uint32_t& r2, uint32_t& r3, uint32_t addr) {
    asm volatile("ldmatrix.sync.aligned.m8n8.x4.shared.b16 {%0,%1,%2,%3}, [%4];"
                 : "=r"(r0), "=r"(r1), "=r"(r2), "=r"(r3) : "r"(addr));
}

__device__ __forceinline__ void mma16816(float* c, const uint32_t* a, const uint32_t* b) {
    asm volatile(
        "mma.sync.aligned.m16n8k16.row.col.f32.f16.f16.f32 "
        "{%0,%1,%2,%3}, {%4,%5,%6,%7}, {%8,%9}, {%0,%1,%2,%3};"
        : "+f"(c[0]), "+f"(c[1]), "+f"(c[2]), "+f"(c[3])
        : "r"(a[0]), "r"(a[1]), "r"(a[2]), "r"(a[3]), "r"(b[0]), "r"(b[1]));
}

__device__ __forceinline__ void cp16(uint32_t saddr, const void* gptr) {
    asm volatile("cp.async.cg.shared.global [%0], [%1], 16;"
                 :: "r"(saddr), "l"(gptr));
}
#define CP_COMMIT() asm volatile("cp.async.commit_group;" ::: "memory")
#define CP_WAIT2()  asm volatile("cp.async.wait_group 2;" ::: "memory")

// ---------------------------------------------------------------------------
// Stage 0: weight transpose + fp16 hi/lo split:  Wt[n][k] = W[k][n]
// ---------------------------------------------------------------------------
__global__ void wtrans_kernel(const float* __restrict__ W0, const float* __restrict__ W1,
                              const float* __restrict__ W2, const float* __restrict__ W3) {
    __shared__ float s[32][33];
    const float* W = (blockIdx.z == 0) ? W0 : (blockIdx.z == 1) ? W1
                   : (blockIdx.z == 2) ? W2 : W3;
    int n0 = blockIdx.x * 32, k0 = blockIdx.y * 32;
    int tx = threadIdx.x, ty = threadIdx.y;   // 32 x 8
#pragma unroll
    for (int i = 0; i < 4; i++) {
        int kk = ty + i * 8;
        s[kk][tx] = W[(size_t)(k0 + kk) * CDIM + n0 + tx];
    }
    __syncthreads();
#pragma unroll
    for (int i = 0; i < 4; i++) {
        int nn = ty + i * 8;
        float v = s[tx][nn];                  // = W[k0+tx][n0+nn]
        size_t o = (size_t)(n0 + nn) * CDIM + k0 + tx;
        __half h = __float2half(v);
        g_wh[blockIdx.z][o] = h;
        g_wl[blockIdx.z][o] = __float2half(v - __half2float(h));
    }
}

// ---------------------------------------------------------------------------
// Stage 1: q_shift + token mixes -> fp16 (xk, xv, xr), float4 vectorized
// ---------------------------------------------------------------------------
union H4 { __half h[4]; uint2 u; };

__device__ __forceinline__ void store_h4(int sel, size_t base, float4 v) {
    H4 o;
    o.h[0] = __float2half(v.x);
    o.h[1] = __float2half(v.y);
    o.h[2] = __float2half(v.z);
    o.h[3] = __float2half(v.w);
    *(uint2*)(&g_a16[sel][base]) = o.u;
}

__global__ void shift_mix_kernel(const float* __restrict__ x,
                                 const float* __restrict__ mix_k,
                                 const float* __restrict__ mix_v,
                                 const float* __restrict__ mix_r) {
    int idx4 = blockIdx.x * blockDim.x + threadIdx.x;
    if (idx4 >= (int)(NELEM / 4)) return;
    int cq = idx4 % (CDIM / 4);
    int sp = idx4 / (CDIM / 4);
    int c  = cq * 4;
    size_t base = (size_t)sp * CDIM + c;
    int wq = sp % WDIM;
    int hq = (sp / WDIM) % HDIM;

    float4 xx = make_float4(0.f, 0.f, 0.f, 0.f);
    int g = c / QC;
    if (g == 0) {
        if (wq > 0)         xx = *(const float4*)(x + base - CDIM);
    } else if (g == 1) {
        if (wq < WDIM - 1)  xx = *(const float4*)(x + base + CDIM);
    } else if (g == 2) {
        if (hq > 0)         xx = *(const float4*)(x + base - (size_t)WDIM * CDIM);
    } else {
        if (hq < HDIM - 1)  xx = *(const float4*)(x + base + (size_t)WDIM * CDIM);
    }

    float4 xc = *(const float4*)(x + base);
    float4 mk = *(const float4*)(mix_k + c);
    float4 mv = *(const float4*)(mix_v + c);
    float4 mr = *(const float4*)(mix_r + c);

    float4 vk, vv, vr;
    vk.x = xc.x * mk.x + xx.x * (1.f - mk.x);
    vk.y = xc.y * mk.y + xx.y * (1.f - mk.y);
    vk.z = xc.z * mk.z + xx.z * (1.f - mk.z);
    vk.w = xc.w * mk.w + xx.w * (1.f - mk.w);
    vv.x = xc.x * mv.x + xx.x * (1.f - mv.x);
    vv.y = xc.y * mv.y + xx.y * (1.f - mv.y);
    vv.z = xc.z * mv.z + xx.z * (1.f - mv.z);
    vv.w = xc.w * mv.w + xx.w * (1.f - mv.w);
    vr.x = xc.x * mr.x + xx.x * (1.f - mr.x);
    vr.y = xc.y * mr.y + xx.y * (1.f - mr.y);
    vr.z = xc.z * mr.z + xx.z * (1.f - mr.z);
    vr.w = xc.w * mr.w + xx.w * (1.f - mr.w);

    store_h4(0, base, vk);
    store_h4(1, base, vv);
    store_h4(2, base, vr);
}

// ---------------------------------------------------------------------------
// Stage 2/5: fp16 tensor-core GEMM via mma.sync (2-pass W hi/lo split).
// CTA tile 128x128, 8 warps (2x4 -> 64x32 each), BK=32, 4-stage cp.async,
// XOR-swizzled 64B-pitch smem, one __syncthreads per k-iter, 2 CTAs/SM.
// ---------------------------------------------------------------------------
#define TILEB 8192                         // 128 rows * 64B
#define STAGEB (3 * TILEB)                 // 24576: [A | Wh | Wl]
#define NSTAGE 4
#define SM_GEMM (NSTAGE * STAGEB)          // 98304

// smem byte offset for (row, 16B-chunk) with XOR swizzle
__device__ __forceinline__ uint32_t swz_off(int row, int cc) {
    return (uint32_t)(row * 64 + ((cc ^ ((row >> 1) & 3)) << 4));
}

__global__ __launch_bounds__(256, 2)
void tc_gemm_kernel(int aSel, float* __restrict__ cOut) {
    extern __shared__ char smem[];
    const uint32_t sb = smem_u32(smem);
    const int tid = threadIdx.x;
    const int w = tid >> 5, l = tid & 31;
    const int wm = w >> 2, wn = w & 3;

    const int s = (aSel < 0) ? (int)blockIdx.z : aSel;
    const int act = (aSel < 0) ? (s == 2 ? 1 : 0) : 0;

    const __half* __restrict__ A  = g_a16[s];
    const __half* __restrict__ Wh = g_wh[s];
    const __half* __restrict__ Wl = g_wl[s];

    const int mrow0 = blockIdx.y * 128;
    const int ncol0 = blockIdx.x * 128;

    float acc[4][4][4];
#pragma unroll
    for (int i = 0; i < 4; i++)
#pragma unroll
        for (int j = 0; j < 4; j++)
#pragma unroll
            for (int q = 0; q < 4; q++) acc[i][j][q] = 0.0f;

    auto issue = [&](int kc, int st) {
        if (kc < 24) {
            uint32_t s0 = sb + st * STAGEB;
#pragma unroll
            for (int j = 0; j < 2; j++) {
                int id = tid + j * 256;          // 0..511
                int row = id >> 2, cc = id & 3;
                size_t gA = (size_t)(mrow0 + row) * CDIM + kc * 32 + cc * 8;
                size_t gB = (size_t)(ncol0 + row) * CDIM + kc * 32 + cc * 8;
                uint32_t so = swz_off(row, cc);
                cp16(s0 + 0 * TILEB + so, A  + gA);
                cp16(s0 + 1 * TILEB + so, Wh + gB);
                cp16(s0 + 2 * TILEB + so, Wl + gB);
            }
        }
        CP_COMMIT();
    };

    issue(0, 0); issue(1, 1); issue(2, 2);

    // per-lane ldmatrix row / chunk invariants
    const int aRow = wm * 64 + (l & 15);
    const int aC0  = l >> 4;                    // 0..1
    const int aSwz = (aRow >> 1) & 3;
    const int bRow = wn * 32 + ((l & 7) | ((l >> 4) << 3));
    const int bC0  = (l >> 3) & 1;
    const int bSwz = (bRow >> 1) & 3;

    for (int kc = 0; kc < 24; kc++) {
        int st = kc & 3;
        CP_WAIT2();
        __syncthreads();
        issue(kc + 3, (kc + 3) & 3);
        uint32_t s0 = sb + st * STAGEB;
#pragma unroll
        for (int ks = 0; ks < 2; ks++) {
            uint32_t a[4][4], bh[2][4], bl[2][4];
            uint32_t aA = s0 + aRow * 64 + (((aC0 + ks * 2) ^ aSwz) << 4);
            uint32_t bA = s0 + TILEB + bRow * 64 + (((bC0 + ks * 2) ^ bSwz) << 4);
#pragma unroll
            for (int am = 0; am < 4; am++)
                ldsm4(a[am][0], a[am][1], a[am][2], a[am][3],
                      aA + am * 1024);                       // +16 rows
#pragma unroll
            for (int bn = 0; bn < 2; bn++) {
                ldsm4(bh[bn][0], bh[bn][1], bh[bn][2], bh[bn][3],
                      bA + bn * 1024);
                ldsm4(bl[bn][0], bl[bn][1], bl[bn][2], bl[bn][3],
                      bA + bn * 1024 + TILEB);
            }
#pragma unroll
            for (int am = 0; am < 4; am++)
#pragma unroll
                for (int an = 0; an < 4; an++) {
                    const uint32_t* bhp = &bh[an >> 1][(an & 1) * 2];
                    const uint32_t* blp = &bl[an >> 1][(an & 1) * 2];
                    mma16816(acc[am][an], a[am], bhp);
                    mma16816(acc[am][an], a[am], blp);
                }
        }
    }

    // Epilogue.  s==0/1 -> fp16 k/v;  s==2 -> sigmoid fp32 sr;  s==3 -> fp32 out.
    __half* __restrict__ Ch = (s == 0) ? g_k16 : g_v16;
    float*  __restrict__ Cf = (s == 2) ? g_sr : cOut;
#pragma unroll
    for (int am = 0; am < 4; am++) {
        int r0 = mrow0 + wm * 64 + am * 16 + (l >> 2);
#pragma unroll
        for (int an = 0; an < 4; an++) {
            int cc = ncol0 + wn * 32 + an * 8 + (l & 3) * 2;
            float v0 = acc[am][an][0], v1 = acc[am][an][1];
            float v2 = acc[am][an][2], v3 = acc[am][an][3];
            if (s <= 1) {
                *(__half2*)(Ch + (size_t)r0 * CDIM + cc) =
                    __floats2half2_rn(v0, v1);
                *(__half2*)(Ch + (size_t)(r0 + 8) * CDIM + cc) =
                    __floats2half2_rn(v2, v3);
            } else {
                if (act == 1) {
                    v0 = 1.0f / (1.0f + __expf(-v0));
                    v1 = 1.0f / (1.0f + __expf(-v1));
                    v2 = 1.0f / (1.0f + __expf(-v2));
                    v3 = 1.0f / (1.0f + __expf(-v3));
                }
                *(float2*)(Cf + (size_t)r0 * CDIM + cc)       = make_float2(v0, v1);
                *(float2*)(Cf + (size_t)(r0 + 8) * CDIM + cc) = make_float2(v2, v3);
            }
        }
    }
}

// ---------------------------------------------------------------------------
// Stage 3: WKV as 3-phase chunked scan (32 chunks of 32 steps), fp16 k/v
// ---------------------------------------------------------------------------
__device__ __forceinline__ void wkv_update(float& p, float& q, float& o,
                                           float w, float kt, float vt) {
    float wo  = w + o;
    float no2 = fmaxf(wo, kt);
    float A2  = __expf(wo - no2);
    float B2  = __expf(kt - no2);
    p = A2 * p + B2 * vt;
    q = A2 * q + B2;
    o = no2;
}

__global__ void wkv_p1_kernel(const float* __restrict__ spatial_decay) {
    int idx = blockIdx.x * blockDim.x + threadIdx.x;   // 0..NCH*LANES-1
    if (idx >= NCH * LANES) return;
    int chunk = idx / LANES;
    int lane  = idx % LANES;
    int c = lane % CDIM, b = lane / CDIM;
    float w = spatial_decay[c] * (1.0f / (float)TDIM);

    const __half* kp = g_k16 + ((size_t)b * TDIM + chunk * CHL) * CDIM + c;
    const __half* vp = g_v16 + ((size_t)b * TDIM + chunk * CHL) * CDIM + c;

    float p = 0.f, q = 0.f, o = -1e38f;
#pragma unroll 4
    for (int t = 0; t < CHL; t++)
        wkv_update(p, q, o, w,
                   __half2float(kp[(size_t)t * CDIM]),
                   __half2float(vp[(size_t)t * CDIM]));

    g_cp[idx] = p; g_cq[idx] = q; g_co[idx] = o;
}

__global__ void wkv_p2_kernel(const float* __restrict__ spatial_decay) {
    int lane = blockIdx.x * blockDim.x + threadIdx.x;
    if (lane >= LANES) return;
    int c = lane % CDIM;
    float wL = spatial_decay[c] * (1.0f / (float)TDIM) * (float)CHL;

    float p = 0.f, q = 0.f, o = -1e38f;
#pragma unroll
    for (int j = 0; j < NCH; j++) {
        int idx = j * LANES + lane;
        g_ip[idx] = p; g_iq[idx] = q; g_io[idx] = o;
        float cp = g_cp[idx], cq = g_cq[idx], co = g_co[idx];
        float ow = o + wL;
        float no = fmaxf(ow, co);
        float A = __expf(ow - no);
        float B = __expf(co - no);
        p = A * p + B * cp;
        q = A * q + B * cq;
        o = no;
    }
}

__global__ void wkv_p3_kernel(const float* __restrict__ spatial_decay,
                              const float* __restrict__ spatial_first) {
    int idx = blockIdx.x * blockDim.x + threadIdx.x;
    if (idx >= NCH * LANES) return;
    int chunk = idx / LANES;
    int lane  = idx % LANES;
    int c = lane % CDIM, b = lane / CDIM;
    float w = spatial_decay[c] * (1.0f / (float)TDIM);
    float u = spatial_first[c] * (1.0f / (float)TDIM);

    const __half* kp = g_k16 + ((size_t)b * TDIM + chunk * CHL) * CDIM + c;
    const __half* vp = g_v16 + ((size_t)b * TDIM + chunk * CHL) * CDIM + c;
    float*        yp = g_y   + ((size_t)b * TDIM + chunk * CHL) * CDIM + c;

    float p = g_ip[idx], q = g_iq[idx], o = g_io[idx];
#pragma unroll 4
    for (int t = 0; t < CHL; t++) {
        float kt = __half2float(kp[(size_t)t * CDIM]);
        float vt = __half2float(vp[(size_t)t * CDIM]);
        float uk = u + kt;
        float no = fmaxf(o, uk);
        float Aa = __expf(o - no);
        float Bb = __expf(uk - no);
        yp[(size_t)t * CDIM] = __fdividef(Aa * p + Bb * vt, Aa * q + Bb);
        wkv_update(p, q, o, w, kt, vt);
    }
}

// ---------------------------------------------------------------------------
// Stage 4: layernorm(y) * sigmoid_r -> z (fp16). Warp per row, 8 rows/block.
// ---------------------------------------------------------------------------
__global__ __launch_bounds__(256)
void ln_gate_kernel(const float* __restrict__ ln_g,
                    const float* __restrict__ ln_b) {
    int wid  = threadIdx.x >> 5;
    int lane = threadIdx.x & 31;
    int row  = blockIdx.x * 8 + wid;
    size_t rbase = (size_t)row * CDIM;

    float4 y4[6];
    float s = 0.f;
#pragma unroll
    for (int i = 0; i < 6; i++) {
        y4[i] = *(const float4*)(g_y + rbase + (size_t)(i * 32 + lane) * 4);
        s += y4[i].x + y4[i].y + y4[i].z + y4[i].w;
    }
#pragma unroll
    for (int off = 16; off > 0; off >>= 1)
        s += __shfl_xor_sync(0xffffffffu, s, off);
    float mu = s * (1.0f / CDIM);

    float ss = 0.f;
#pragma unroll
    for (int i = 0; i < 6; i++) {
        float d0 = y4[i].x - mu, d1 = y4[i].y - mu;
        float d2 = y4[i].z - mu, d3 = y4[i].w - mu;
        ss += d0 * d0 + d1 * d1 + d2 * d2 + d3 * d3;
    }
#pragma unroll
    for (int off = 16; off > 0; off >>= 1)
        ss += __shfl_xor_sync(0xffffffffu, ss, off);
    float rstd = rsqrtf(ss * (1.0f / CDIM) + 1e-5f);

#pragma unroll
    for (int i = 0; i < 6; i++) {
        int c = (i * 32 + lane) * 4;
        float4 sr4 = *(const float4*)(g_sr + rbase + c);
        float4 g4  = *(const float4*)(ln_g + c);
        float4 b4  = *(const float4*)(ln_b + c);
        float4 z;
        z.x = sr4.x * ((y4[i].x - mu) * rstd * g4.x + b4.x);
        z.y = sr4.y * ((y4[i].y - mu) * rstd * g4.y + b4.y);
        z.z = sr4.z * ((y4[i].z - mu) * rstd * g4.z + b4.z);
        z.w = sr4.w * ((y4[i].w - mu) * rstd * g4.w + b4.w);
        store_h4(3, rbase + c, z);
    }
}

// ---------------------------------------------------------------------------
// Launch
// ---------------------------------------------------------------------------
extern "C" void kernel_launch(void* const* d_in, const int* in_sizes, int n_in,
                              void* d_out, int out_size) {
    const float* x   = (const float*)d_in[0];
    const float* sd  = (const float*)d_in[3];
    const float* sf  = (const float*)d_in[4];
    const float* mk  = (const float*)d_in[5];
    const float* mv  = (const float*)d_in[6];
    const float* mr  = (const float*)d_in[7];
    const float* Wk  = (const float*)d_in[8];
    const float* Wv  = (const float*)d_in[9];
    const float* Wr  = (const float*)d_in[10];
    const float* Wo  = (const float*)d_in[11];
    const float* lg  = (const float*)d_in[12];
    const float* lb  = (const float*)d_in[13];
    float* out = (float*)d_out;

    cudaFuncSetAttribute(tc_gemm_kernel,
                         cudaFuncAttributeMaxDynamicSharedMemorySize, SM_GEMM);

    // 0. transpose + split weights (fp16 hi/lo)
    {
        dim3 blk(32, 8);
        dim3 grd(CDIM / 32, CDIM / 32, 4);
        wtrans_kernel<<<grd, blk>>>(Wk, Wv, Wr, Wo);
    }

    // 1. q_shift + mixes -> fp16
    {
        int n4 = (int)(NELEM / 4);
        shift_mix_kernel<<<(n4 + 255) / 256, 256>>>(x, mk, mv, mr);
    }

    // 2. fused k / v / sr GEMMs (z = 0,1,2)
    {
        dim3 gg(CDIM / 128, MROWS / 128, 3);
        tc_gemm_kernel<<<gg, 256, SM_GEMM>>>(-1, nullptr);
    }

    // 3. WKV chunked scan (fp16 k/v inputs)
    wkv_p1_kernel<<<(NCH * LANES) / 256, 256>>>(sd);
    wkv_p2_kernel<<<(LANES + 255) / 256, 256>>>(sd);
    wkv_p3_kernel<<<(NCH * LANES) / 256, 256>>>(sd, sf);

    // 4. layernorm + gate -> z (fp16)
    ln_gate_kernel<<<MROWS / 8, 256>>>(lg, lb);

    // 5. output projection -> d_out
    {
        dim3 gg(CDIM / 128, MROWS / 128, 1);
        tc_gemm_kernel<<<gg, 256, SM_GEMM>>>(3, out);
    }
}

// round 7
// speedup vs baseline: 8.1716x; 1.4883x over previous
#include <cuda_runtime.h>
#include <cuda_fp16.h>
#include <stdint.h>
#include <math.h>

// Problem constants (fixed by dataset: x is (16, 1024, 768), h=w=32)
#define BDIM 16
#define HDIM 32
#define WDIM 32
#define TDIM (HDIM * WDIM)          // 1024
#define CDIM 768
#define MROWS (BDIM * TDIM)         // 16384
#define QC (CDIM / 4)               // 192

#define NELEM ((size_t)MROWS * CDIM)   // 12,582,912

// WKV chunked-scan config
#define LANES (BDIM * CDIM)         // 12288
#define NCH 32
#define CHL (TDIM / NCH)            // 32

// ---------------------------------------------------------------------------
// Scratch (device globals; no allocation allowed)
// ---------------------------------------------------------------------------
__device__ __half g_a16[4][NELEM];              // 0=xk 1=xv 2=xr 3=z (fp16)
__device__ __half g_wh[4][CDIM * CDIM];         // W^T [N][K] fp16
__device__ __half g_k16[NELEM];
__device__ __half g_v16[NELEM];
__device__ float g_sr[NELEM];
__device__ float g_y [NELEM];
// wkv chunk-local states and per-chunk initial states
__device__ float g_cp[NCH * LANES], g_cq[NCH * LANES], g_co[NCH * LANES];
__device__ float g_ip[NCH * LANES], g_iq[NCH * LANES], g_io[NCH * LANES];

// ---------------------------------------------------------------------------
// PTX helpers (base sm_103-compatible: mma.sync / ldmatrix / cp.async)
// ---------------------------------------------------------------------------
__device__ __forceinline__ uint32_t smem_u32(const void* p) {
    uint32_t a;
    asm("{ .reg .u64 t; cvta.to.shared.u64 t, %1; cvt.u32.u64 %0, t; }"
        : "=r"(a) : "l"(p));
    return a;
}

__device__ __forceinline__ void ldsm4(uint32_t& r0, uint32_t& r1,
                                      uint32_t& r2, uint32_t& r3, uint32_t addr) {
    asm volatile("ldmatrix.sync.aligned.m8n8.x4.shared.b16 {%0,%1,%2,%3}, [%4];"
                 : "=r"(r0), "=r"(r1), "=r"(r2), "=r"(r3) : "r"(addr));
}

__device__ __forceinline__ void mma16816(float* c, const uint32_t* a, const uint32_t* b) {
    asm volatile(
        "mma.sync.aligned.m16n8k16.row.col.f32.f16.f16.f32 "
        "{%0,%1,%2,%3}, {%4,%5,%6,%7}, {%8,%9}, {%0,%1,%2,%3};"
        : "+f"(c[0]), "+f"(c[1]), "+f"(c[2]), "+f"(c[3])
        : "r"(a[0]), "r"(a[1]), "r"(a[2]), "r"(a[3]), "r"(b[0]), "r"(b[1]));
}

__device__ __forceinline__ void cp16(uint32_t saddr, const void* gptr) {
    asm volatile("cp.async.cg.shared.global [%0], [%1], 16;"
                 :: "r"(saddr), "l"(gptr));
}
#define CP_COMMIT() asm volatile("cp.async.commit_group;" ::: "memory")
#define CP_WAIT2()  asm volatile("cp.async.wait_group 2;" ::: "memory")

// ---------------------------------------------------------------------------
// Stage 0: weight transpose + fp16:  Wt[n][k] = W[k][n]
// ---------------------------------------------------------------------------
__global__ void wtrans_kernel(const float* __restrict__ W0, const float* __restrict__ W1,
                              const float* __restrict__ W2, const float* __restrict__ W3) {
    __shared__ float s[32][33];
    const float* W = (blockIdx.z == 0) ? W0 : (blockIdx.z == 1) ? W1
                   : (blockIdx.z == 2) ? W2 : W3;
    int n0 = blockIdx.x * 32, k0 = blockIdx.y * 32;
    int tx = threadIdx.x, ty = threadIdx.y;   // 32 x 8
#pragma unroll
    for (int i = 0; i < 4; i++) {
        int kk = ty + i * 8;
        s[kk][tx] = W[(size_t)(k0 + kk) * CDIM + n0 + tx];
    }
    __syncthreads();
#pragma unroll
    for (int i = 0; i < 4; i++) {
        int nn = ty + i * 8;
        float v = s[tx][nn];                  // = W[k0+tx][n0+nn]
        g_wh[blockIdx.z][(size_t)(n0 + nn) * CDIM + k0 + tx] = __float2half(v);
    }
}

// ---------------------------------------------------------------------------
// Stage 1: q_shift + token mixes -> fp16 (xk, xv, xr), float4 vectorized
// ---------------------------------------------------------------------------
union H4 { __half h[4]; uint2 u; };

__device__ __forceinline__ void store_h4(int sel, size_t base, float4 v) {
    H4 o;
    o.h[0] = __float2half(v.x);
    o.h[1] = __float2half(v.y);
    o.h[2] = __float2half(v.z);
    o.h[3] = __float2half(v.w);
    *(uint2*)(&g_a16[sel][base]) = o.u;
}

__global__ void shift_mix_kernel(const float* __restrict__ x,
                                 const float* __restrict__ mix_k,
                                 const float* __restrict__ mix_v,
                                 const float* __restrict__ mix_r) {
    int idx4 = blockIdx.x * blockDim.x + threadIdx.x;
    if (idx4 >= (int)(NELEM / 4)) return;
    int cq = idx4 % (CDIM / 4);
    int sp = idx4 / (CDIM / 4);
    int c  = cq * 4;
    size_t base = (size_t)sp * CDIM + c;
    int wq = sp % WDIM;
    int hq = (sp / WDIM) % HDIM;

    float4 xx = make_float4(0.f, 0.f, 0.f, 0.f);
    int g = c / QC;
    if (g == 0) {
        if (wq > 0)         xx = *(const float4*)(x + base - CDIM);
    } else if (g == 1) {
        if (wq < WDIM - 1)  xx = *(const float4*)(x + base + CDIM);
    } else if (g == 2) {
        if (hq > 0)         xx = *(const float4*)(x + base - (size_t)WDIM * CDIM);
    } else {
        if (hq < HDIM - 1)  xx = *(const float4*)(x + base + (size_t)WDIM * CDIM);
    }

    float4 xc = *(const float4*)(x + base);
    float4 mk = *(const float4*)(mix_k + c);
    float4 mv = *(const float4*)(mix_v + c);
    float4 mr = *(const float4*)(mix_r + c);

    float4 vk, vv, vr;
    vk.x = xc.x * mk.x + xx.x * (1.f - mk.x);
    vk.y = xc.y * mk.y + xx.y * (1.f - mk.y);
    vk.z = xc.z * mk.z + xx.z * (1.f - mk.z);
    vk.w = xc.w * mk.w + xx.w * (1.f - mk.w);
    vv.x = xc.x * mv.x + xx.x * (1.f - mv.x);
    vv.y = xc.y * mv.y + xx.y * (1.f - mv.y);
    vv.z = xc.z * mv.z + xx.z * (1.f - mv.z);
    vv.w = xc.w * mv.w + xx.w * (1.f - mv.w);
    vr.x = xc.x * mr.x + xx.x * (1.f - mr.x);
    vr.y = xc.y * mr.y + xx.y * (1.f - mr.y);
    vr.z = xc.z * mr.z + xx.z * (1.f - mr.z);
    vr.w = xc.w * mr.w + xx.w * (1.f - mr.w);

    store_h4(0, base, vk);
    store_h4(1, base, vv);
    store_h4(2, base, vr);
}

// ---------------------------------------------------------------------------
// Stage 2/5: fp16 tensor-core GEMM via mma.sync (single pass).
// CTA tile 128x128, 8 warps (2x4 -> 64x32 each), BK=32, 4-stage cp.async,
// XOR-swizzled 64B-pitch smem, one __syncthreads per k-iter, 2 CTAs/SM.
// ---------------------------------------------------------------------------
#define TILEB 8192                         // 128 rows * 64B
#define STAGEB (2 * TILEB)                 // 16384: [A | Wh]
#define NSTAGE 4
#define SM_GEMM (NSTAGE * STAGEB)          // 65536

// smem byte offset for (row, 16B-chunk) with XOR swizzle
__device__ __forceinline__ uint32_t swz_off(int row, int cc) {
    return (uint32_t)(row * 64 + ((cc ^ ((row >> 1) & 3)) << 4));
}

__global__ __launch_bounds__(256, 2)
void tc_gemm_kernel(int aSel, float* __restrict__ cOut) {
    extern __shared__ char smem[];
    const uint32_t sb = smem_u32(smem);
    const int tid = threadIdx.x;
    const int w = tid >> 5, l = tid & 31;
    const int wm = w >> 2, wn = w & 3;

    const int s = (aSel < 0) ? (int)blockIdx.z : aSel;
    const int act = (aSel < 0) ? (s == 2 ? 1 : 0) : 0;

    const __half* __restrict__ A  = g_a16[s];
    const __half* __restrict__ Wh = g_wh[s];

    const int mrow0 = blockIdx.y * 128;
    const int ncol0 = blockIdx.x * 128;

    float acc[4][4][4];
#pragma unroll
    for (int i = 0; i < 4; i++)
#pragma unroll
        for (int j = 0; j < 4; j++)
#pragma unroll
            for (int q = 0; q < 4; q++) acc[i][j][q] = 0.0f;

    auto issue = [&](int kc, int st) {
        if (kc < 24) {
            uint32_t s0 = sb + st * STAGEB;
#pragma unroll
            for (int j = 0; j < 2; j++) {
                int id = tid + j * 256;          // 0..511
                int row = id >> 2, cc = id & 3;
                size_t gA = (size_t)(mrow0 + row) * CDIM + kc * 32 + cc * 8;
                size_t gB = (size_t)(ncol0 + row) * CDIM + kc * 32 + cc * 8;
                uint32_t so = swz_off(row, cc);
                cp16(s0 + 0 * TILEB + so, A  + gA);
                cp16(s0 + 1 * TILEB + so, Wh + gB);
            }
        }
        CP_COMMIT();
    };

    issue(0, 0); issue(1, 1); issue(2, 2);

    // per-lane ldmatrix row / chunk invariants
    const int aRow = wm * 64 + (l & 15);
    const int aC0  = l >> 4;                    // 0..1
    const int aSwz = (aRow >> 1) & 3;
    const int bRow = wn * 32 + ((l & 7) | ((l >> 4) << 3));
    const int bC0  = (l >> 3) & 1;
    const int bSwz = (bRow >> 1) & 3;

    for (int kc = 0; kc < 24; kc++) {
        int st = kc & 3;
        CP_WAIT2();
        __syncthreads();
        issue(kc + 3, (kc + 3) & 3);
        uint32_t s0 = sb + st * STAGEB;
#pragma unroll
        for (int ks = 0; ks < 2; ks++) {
            uint32_t a[4][4], bh[2][4];
            uint32_t aA = s0 + aRow * 64 + (((aC0 + ks * 2) ^ aSwz) << 4);
            uint32_t bA = s0 + TILEB + bRow * 64 + (((bC0 + ks * 2) ^ bSwz) << 4);
#pragma unroll
            for (int am = 0; am < 4; am++)
                ldsm4(a[am][0], a[am][1], a[am][2], a[am][3],
                      aA + am * 1024);                       // +16 rows
#pragma unroll
            for (int bn = 0; bn < 2; bn++)
                ldsm4(bh[bn][0], bh[bn][1], bh[bn][2], bh[bn][3],
                      bA + bn * 1024);
#pragma unroll
            for (int am = 0; am < 4; am++)
#pragma unroll
                for (int an = 0; an < 4; an++)
                    mma16816(acc[am][an], a[am], &bh[an >> 1][(an & 1) * 2]);
        }
    }

    // Epilogue.  s==0/1 -> fp16 k/v;  s==2 -> sigmoid fp32 sr;  s==3 -> fp32 out.
    __half* __restrict__ Ch = (s == 0) ? g_k16 : g_v16;
    float*  __restrict__ Cf = (s == 2) ? g_sr : cOut;
#pragma unroll
    for (int am = 0; am < 4; am++) {
        int r0 = mrow0 + wm * 64 + am * 16 + (l >> 2);
#pragma unroll
        for (int an = 0; an < 4; an++) {
            int cc = ncol0 + wn * 32 + an * 8 + (l & 3) * 2;
            float v0 = acc[am][an][0], v1 = acc[am][an][1];
            float v2 = acc[am][an][2], v3 = acc[am][an][3];
            if (s <= 1) {
                *(__half2*)(Ch + (size_t)r0 * CDIM + cc) =
                    __floats2half2_rn(v0, v1);
                *(__half2*)(Ch + (size_t)(r0 + 8) * CDIM + cc) =
                    __floats2half2_rn(v2, v3);
            } else {
                if (act == 1) {
                    v0 = 1.0f / (1.0f + __expf(-v0));
                    v1 = 1.0f / (1.0f + __expf(-v1));
                    v2 = 1.0f / (1.0f + __expf(-v2));
                    v3 = 1.0f / (1.0f + __expf(-v3));
                }
                *(float2*)(Cf + (size_t)r0 * CDIM + cc)       = make_float2(v0, v1);
                *(float2*)(Cf + (size_t)(r0 + 8) * CDIM + cc) = make_float2(v2, v3);
            }
        }
    }
}

// ---------------------------------------------------------------------------
// Stage 3: WKV as 3-phase chunked scan (32 chunks of 32 steps), fp16 k/v
// ---------------------------------------------------------------------------
__device__ __forceinline__ void wkv_update(float& p, float& q, float& o,
                                           float w, float kt, float vt) {
    float wo  = w + o;
    float no2 = fmaxf(wo, kt);
    float A2  = __expf(wo - no2);
    float B2  = __expf(kt - no2);
    p = A2 * p + B2 * vt;
    q = A2 * q + B2;
    o = no2;
}

__global__ void wkv_p1_kernel(const float* __restrict__ spatial_decay) {
    int idx = blockIdx.x * blockDim.x + threadIdx.x;   // 0..NCH*LANES-1
    if (idx >= NCH * LANES) return;
    int chunk = idx / LANES;
    int lane  = idx % LANES;
    int c = lane % CDIM, b = lane / CDIM;
    float w = spatial_decay[c] * (1.0f / (float)TDIM);

    const __half* kp = g_k16 + ((size_t)b * TDIM + chunk * CHL) * CDIM + c;
    const __half* vp = g_v16 + ((size_t)b * TDIM + chunk * CHL) * CDIM + c;

    float p = 0.f, q = 0.f, o = -1e38f;
#pragma unroll 4
    for (int t = 0; t < CHL; t++)
        wkv_update(p, q, o, w,
                   __half2float(kp[(size_t)t * CDIM]),
                   __half2float(vp[(size_t)t * CDIM]));

    g_cp[idx] = p; g_cq[idx] = q; g_co[idx] = o;
}

__global__ void wkv_p2_kernel(const float* __restrict__ spatial_decay) {
    int lane = blockIdx.x * blockDim.x + threadIdx.x;
    if (lane >= LANES) return;
    int c = lane % CDIM;
    float wL = spatial_decay[c] * (1.0f / (float)TDIM) * (float)CHL;

    float p = 0.f, q = 0.f, o = -1e38f;
#pragma unroll
    for (int j = 0; j < NCH; j++) {
        int idx = j * LANES + lane;
        g_ip[idx] = p; g_iq[idx] = q; g_io[idx] = o;
        float cp = g_cp[idx], cq = g_cq[idx], co = g_co[idx];
        float ow = o + wL;
        float no = fmaxf(ow, co);
        float A = __expf(ow - no);
        float B = __expf(co - no);
        p = A * p + B * cp;
        q = A * q + B * cq;
        o = no;
    }
}

__global__ void wkv_p3_kernel(const float* __restrict__ spatial_decay,
                              const float* __restrict__ spatial_first) {
    int idx = blockIdx.x * blockDim.x + threadIdx.x;
    if (idx >= NCH * LANES) return;
    int chunk = idx / LANES;
    int lane  = idx % LANES;
    int c = lane % CDIM, b = lane / CDIM;
    float w = spatial_decay[c] * (1.0f / (float)TDIM);
    float u = spatial_first[c] * (1.0f / (float)TDIM);

    const __half* kp = g_k16 + ((size_t)b * TDIM + chunk * CHL) * CDIM + c;
    const __half* vp = g_v16 + ((size_t)b * TDIM + chunk * CHL) * CDIM + c;
    float*        yp = g_y   + ((size_t)b * TDIM + chunk * CHL) * CDIM + c;

    float p = g_ip[idx], q = g_iq[idx], o = g_io[idx];
#pragma unroll 4
    for (int t = 0; t < CHL; t++) {
        float kt = __half2float(kp[(size_t)t * CDIM]);
        float vt = __half2float(vp[(size_t)t * CDIM]);
        float uk = u + kt;
        float no = fmaxf(o, uk);
        float Aa = __expf(o - no);
        float Bb = __expf(uk - no);
        yp[(size_t)t * CDIM] = __fdividef(Aa * p + Bb * vt, Aa * q + Bb);
        wkv_update(p, q, o, w, kt, vt);
    }
}

// ---------------------------------------------------------------------------
// Stage 4: layernorm(y) * sigmoid_r -> z (fp16). Warp per row, 8 rows/block.
// ---------------------------------------------------------------------------
__global__ __launch_bounds__(256)
void ln_gate_kernel(const float* __restrict__ ln_g,
                    const float* __restrict__ ln_b) {
    int wid  = threadIdx.x >> 5;
    int lane = threadIdx.x & 31;
    int row  = blockIdx.x * 8 + wid;
    size_t rbase = (size_t)row * CDIM;

    float4 y4[6];
    float s = 0.f;
#pragma unroll
    for (int i = 0; i < 6; i++) {
        y4[i] = *(const float4*)(g_y + rbase + (size_t)(i * 32 + lane) * 4);
        s += y4[i].x + y4[i].y + y4[i].z + y4[i].w;
    }
#pragma unroll
    for (int off = 16; off > 0; off >>= 1)
        s += __shfl_xor_sync(0xffffffffu, s, off);
    float mu = s * (1.0f / CDIM);

    float ss = 0.f;
#pragma unroll
    for (int i = 0; i < 6; i++) {
        float d0 = y4[i].x - mu, d1 = y4[i].y - mu;
        float d2 = y4[i].z - mu, d3 = y4[i].w - mu;
        ss += d0 * d0 + d1 * d1 + d2 * d2 + d3 * d3;
    }
#pragma unroll
    for (int off = 16; off > 0; off >>= 1)
        ss += __shfl_xor_sync(0xffffffffu, ss, off);
    float rstd = rsqrtf(ss * (1.0f / CDIM) + 1e-5f);

#pragma unroll
    for (int i = 0; i < 6; i++) {
        int c = (i * 32 + lane) * 4;
        float4 sr4 = *(const float4*)(g_sr + rbase + c);
        float4 g4  = *(const float4*)(ln_g + c);
        float4 b4  = *(const float4*)(ln_b + c);
        float4 z;
        z.x = sr4.x * ((y4[i].x - mu) * rstd * g4.x + b4.x);
        z.y = sr4.y * ((y4[i].y - mu) * rstd * g4.y + b4.y);
        z.z = sr4.z * ((y4[i].z - mu) * rstd * g4.z + b4.z);
        z.w = sr4.w * ((y4[i].w - mu) * rstd * g4.w + b4.w);
        store_h4(3, rbase + c, z);
    }
}

// ---------------------------------------------------------------------------
// Launch
// ---------------------------------------------------------------------------
extern "C" void kernel_launch(void* const* d_in, const int* in_sizes, int n_in,
                              void* d_out, int out_size) {
    const float* x   = (const float*)d_in[0];
    const float* sd  = (const float*)d_in[3];
    const float* sf  = (const float*)d_in[4];
    const float* mk  = (const float*)d_in[5];
    const float* mv  = (const float*)d_in[6];
    const float* mr  = (const float*)d_in[7];
    const float* Wk  = (const float*)d_in[8];
    const float* Wv  = (const float*)d_in[9];
    const float* Wr  = (const float*)d_in[10];
    const float* Wo  = (const float*)d_in[11];
    const float* lg  = (const float*)d_in[12];
    const float* lb  = (const float*)d_in[13];
    float* out = (float*)d_out;

    cudaFuncSetAttribute(tc_gemm_kernel,
                         cudaFuncAttributeMaxDynamicSharedMemorySize, SM_GEMM);

    // 0. transpose weights -> fp16
    {
        dim3 blk(32, 8);
        dim3 grd(CDIM / 32, CDIM / 32, 4);
        wtrans_kernel<<<grd, blk>>>(Wk, Wv, Wr, Wo);
    }

    // 1. q_shift + mixes -> fp16
    {
        int n4 = (int)(NELEM / 4);
        shift_mix_kernel<<<(n4 + 255) / 256, 256>>>(x, mk, mv, mr);
    }

    // 2. fused k / v / sr GEMMs (z = 0,1,2)
    {
        dim3 gg(CDIM / 128, MROWS / 128, 3);
        tc_gemm_kernel<<<gg, 256, SM_GEMM>>>(-1, nullptr);
    }

    // 3. WKV chunked scan (fp16 k/v inputs)
    wkv_p1_kernel<<<(NCH * LANES) / 256, 256>>>(sd);
    wkv_p2_kernel<<<(LANES + 255) / 256, 256>>>(sd);
    wkv_p3_kernel<<<(NCH * LANES) / 256, 256>>>(sd, sf);

    // 4. layernorm + gate -> z (fp16)
    ln_gate_kernel<<<MROWS / 8, 256>>>(lg, lb);

    // 5. output projection -> d_out
    {
        dim3 gg(CDIM / 128, MROWS / 128, 1);
        tc_gemm_kernel<<<gg, 256, SM_GEMM>>>(3, out);
    }
}